// round 13
// baseline (speedup 1.0000x reference)
#include <cuda_runtime.h>
#include <cuda_fp16.h>

#define T_STEPS 8192
#define IN_DIM  2048
#define MEM     2048
#define NCOL    10240   // 5*MEM
#define NCTA    148
#define NT      448     // 14 warps

// ---------------- device-global scratch ----------------
__device__ __align__(16) __half g_Whh[(size_t)8192 * 2048];   // fp16 Wh  (33.5 MB)
__device__ __align__(16) __half g_Wmh[(size_t)2048 * 2048];   // fp16 Wm  ( 8.4 MB)
__device__ __align__(16) __half g_inh[(size_t)8192 * 2048];   // fp16 inputs
__device__ __align__(16) __half g_wxh[(size_t)10240 * 2048];  // fp16 Wx
__device__ float  g_xg[(size_t)T_STEPS * NCOL];               // input projections
__device__ __align__(16) float    g_h[MEM];                   // fp32 h (final step only)
__device__ __align__(16) unsigned g_hhT[2][MEM];              // tagged h: (tag<<16)|fp16
__device__ __align__(16) unsigned g_mhT[MEM];                 // tagged m: (tag<<16)|fp16
__device__ unsigned int g_bar2;                               // final-step barrier only

// ---------------- init (graph-replay safe) ----------------
__global__ void k_init() {
    int i = blockIdx.x * blockDim.x + threadIdx.x;
    if (i == 0) g_bar2 = 0u;
    if (i < MEM) {
        g_h[i] = 0.f;
        g_hhT[0][i] = 0u;   // tag 0, value 0 == expected at t=0
        g_hhT[1][i] = 0u;
        g_mhT[i]    = 0u;   // m expects tag >= 1, never matches stale 0
    }
}

// ---------------- fp32 -> fp16 conversions ----------------
__global__ void k_convert(const float* __restrict__ Wh, const float* __restrict__ Wm) {
    const int n1 = 8192 * 2048, n2 = 2048 * 2048;
    int stride = gridDim.x * blockDim.x;
    for (int i = blockIdx.x * blockDim.x + threadIdx.x; i < n1; i += stride)
        g_Whh[i] = __float2half_rn(Wh[i]);
    for (int i = blockIdx.x * blockDim.x + threadIdx.x; i < n2; i += stride)
        g_Wmh[i] = __float2half_rn(Wm[i]);
}
__global__ void k_convert2(const float* __restrict__ inp, const float* __restrict__ Wx) {
    const int n1 = 8192 * 2048, n2 = 10240 * 2048;
    int stride = gridDim.x * blockDim.x;
    for (int i = blockIdx.x * blockDim.x + threadIdx.x; i < n1; i += stride)
        g_inh[i] = __float2half_rn(inp[i]);
    for (int i = blockIdx.x * blockDim.x + threadIdx.x; i < n2; i += stride)
        g_wxh[i] = __float2half_rn(Wx[i]);
}

// ---------------- cp.async helpers ----------------
__device__ __forceinline__ void cp_async16(unsigned smem, const void* gptr) {
    asm volatile("cp.async.cg.shared.global [%0], [%1], 16;" :: "r"(smem), "l"(gptr));
}
__device__ __forceinline__ void cp_commit() { asm volatile("cp.async.commit_group;"); }
__device__ __forceinline__ void cp_wait1()  { asm volatile("cp.async.wait_group 1;"); }
__device__ __forceinline__ void cp_wait0()  { asm volatile("cp.async.wait_group 0;"); }

// ---------------- tensor-core GEMM (2-stage cp.async pipeline, validated R10/R12) ----------------
#define LDT 40

__global__ __launch_bounds__(256) void k_gemm16(const __half* __restrict__ A,
                                                const __half* __restrict__ B,
                                                const float* __restrict__ bias) {
    __shared__ __half As[2][128 * LDT];
    __shared__ __half Bs[2][128 * LDT];
    const int tid = threadIdx.x;
    const int warp = tid >> 5, lane = tid & 31;
    const int bm = blockIdx.y * 128, bn = blockIdx.x * 128;
    const int wm = (warp >> 2) * 64, wn = (warp & 3) * 32;
    const int grp = lane >> 2, tig = lane & 3;

    const unsigned sA = (unsigned)__cvta_generic_to_shared(&As[0][0]);
    const unsigned sB = (unsigned)__cvta_generic_to_shared(&Bs[0][0]);
    const unsigned stageBytes = 128 * LDT * 2;

    float acc[4][4][4];
#pragma unroll
    for (int mt = 0; mt < 4; mt++)
#pragma unroll
        for (int nt = 0; nt < 4; nt++)
#pragma unroll
            for (int k = 0; k < 4; k++) acc[mt][nt][k] = 0.f;

    const int row0 = (tid + 0)   >> 2, c40 = (tid + 0)   & 3;
    const int row1 = (tid + 256) >> 2, c41 = (tid + 256) & 3;

    auto issue = [&](int k0, int s) {
        unsigned a0 = sA + s * stageBytes + (row0 * LDT + c40 * 8) * 2;
        unsigned a1 = sA + s * stageBytes + (row1 * LDT + c41 * 8) * 2;
        unsigned b0 = sB + s * stageBytes + (row0 * LDT + c40 * 8) * 2;
        unsigned b1 = sB + s * stageBytes + (row1 * LDT + c41 * 8) * 2;
        cp_async16(a0, A + (size_t)(bm + row0) * IN_DIM + k0 + c40 * 8);
        cp_async16(a1, A + (size_t)(bm + row1) * IN_DIM + k0 + c41 * 8);
        cp_async16(b0, B + (size_t)(bn + row0) * IN_DIM + k0 + c40 * 8);
        cp_async16(b1, B + (size_t)(bn + row1) * IN_DIM + k0 + c41 * 8);
        cp_commit();
    };

    const int NTILE = IN_DIM / 32;
    issue(0, 0);

    for (int it = 0; it < NTILE; ++it) {
        int s = it & 1;
        if (it + 1 < NTILE) { issue((it + 1) * 32, s ^ 1); cp_wait1(); }
        else                { cp_wait0(); }
        __syncthreads();

        const __half* Ab = &As[s][0];
        const __half* Bb = &Bs[s][0];
#pragma unroll
        for (int ks = 0; ks < 32; ks += 16) {
            unsigned bf[4][2];
#pragma unroll
            for (int nt = 0; nt < 4; nt++) {
                const __half* bp = &Bb[(wn + nt * 8 + grp) * LDT + tig * 2 + ks];
                bf[nt][0] = *(const unsigned*)bp;
                bf[nt][1] = *(const unsigned*)(bp + 8);
            }
#pragma unroll
            for (int mt = 0; mt < 4; mt++) {
                const __half* ap = &Ab[(wm + mt * 16 + grp) * LDT + tig * 2 + ks];
                unsigned a0 = *(const unsigned*)ap;
                unsigned a1 = *(const unsigned*)(ap + 8 * LDT);
                unsigned a2 = *(const unsigned*)(ap + 8);
                unsigned a3 = *(const unsigned*)(ap + 8 * LDT + 8);
#pragma unroll
                for (int nt = 0; nt < 4; nt++) {
                    asm volatile(
                        "mma.sync.aligned.m16n8k16.row.col.f32.f16.f16.f32 "
                        "{%0,%1,%2,%3}, {%4,%5,%6,%7}, {%8,%9}, {%0,%1,%2,%3};"
                        : "+f"(acc[mt][nt][0]), "+f"(acc[mt][nt][1]),
                          "+f"(acc[mt][nt][2]), "+f"(acc[mt][nt][3])
                        : "r"(a0), "r"(a1), "r"(a2), "r"(a3),
                          "r"(bf[nt][0]), "r"(bf[nt][1]));
                }
            }
        }
        __syncthreads();
    }

#pragma unroll
    for (int mt = 0; mt < 4; mt++) {
        int m = bm + wm + mt * 16 + grp;
#pragma unroll
        for (int nt = 0; nt < 4; nt++) {
            int n = bn + wn + nt * 8 + tig * 2;
            float2 bv = *(const float2*)(bias + n);
            float2 o0 = { acc[mt][nt][0] + bv.x, acc[mt][nt][1] + bv.y };
            float2 o1 = { acc[mt][nt][2] + bv.x, acc[mt][nt][3] + bv.y };
            *(float2*)(g_xg + (size_t)m * NCOL + n) = o0;
            *(float2*)(g_xg + (size_t)(m + 8) * NCOL + n) = o1;
        }
    }
}

// ---------------- sync / load / math helpers ----------------
__device__ __forceinline__ unsigned ld_relaxed(const unsigned* p) {
    unsigned v;
    asm volatile("ld.relaxed.gpu.global.u32 %0, [%1];" : "=r"(v) : "l"(p) : "memory");
    return v;
}
__device__ __forceinline__ unsigned ld_acq(const unsigned* p) {
    unsigned v;
    asm volatile("ld.acquire.gpu.global.u32 %0, [%1];" : "=r"(v) : "l"(p) : "memory");
    return v;
}
__device__ __forceinline__ void st_relaxed(unsigned* p, unsigned v) {
    asm volatile("st.relaxed.gpu.global.u32 [%0], %1;" :: "l"(p), "r"(v) : "memory");
}
__device__ __forceinline__ void red_rel(unsigned* p) {
    asm volatile("red.release.gpu.global.add.u32 [%0], 1;" :: "l"(p) : "memory");
}
__device__ __forceinline__ unsigned ldcg1(const unsigned* p) {
    unsigned v;
    asm volatile("ld.global.cg.u32 %0, [%1];" : "=r"(v) : "l"(p) : "memory");
    return v;
}
__device__ __forceinline__ float sigf(float x) { return 1.0f / (1.0f + __expf(-x)); }
__device__ __forceinline__ float tanhf_fast(float x) {
    return 1.0f - __fdividef(2.0f, 1.0f + __expf(2.0f * x));
}
__device__ __forceinline__ float wsum(float v) {
#pragma unroll
    for (int o = 16; o > 0; o >>= 1) v += __shfl_xor_sync(0xffffffffu, v, o);
    return v;
}
__device__ __forceinline__ __half2 h2u(unsigned u) { return *reinterpret_cast<__half2*>(&u); }

__device__ __forceinline__ void mac8(uint4 wv, uint4 hv, float& ax, float& ay) {
    __half2 p = __hmul2(h2u(wv.x), h2u(hv.x));
    p = __hfma2(h2u(wv.y), h2u(hv.y), p);
    p = __hfma2(h2u(wv.z), h2u(hv.z), p);
    p = __hfma2(h2u(wv.w), h2u(hv.w), p);
    float2 f = __half22float2(p);
    ax += f.x; ay += f.y;
}

// tagged-word staging: poll until tag matches, then deposit fp16 bits into SMEM
__device__ __forceinline__ void stage_tagged(const unsigned* __restrict__ src,
                                             unsigned short* __restrict__ dst,
                                             unsigned exp, int tid) {
    for (int i = tid; i < MEM; i += NT) {
        unsigned v = ld_relaxed(src + i);
        while ((v >> 16) != exp) v = ld_relaxed(src + i);
        dst[i] = (unsigned short)v;
    }
}

// ---------------- persistent recurrent kernel (dataflow-synced) ----------------
#define DYN_SMEM (42 * 4096 + 4096 + 4096)

__global__ __launch_bounds__(NT, 1) void k_recur(const float* __restrict__ bh,
                                                 const float* __restrict__ bmv,
                                                 float* __restrict__ out) {
    extern __shared__ __align__(16) unsigned char dyn[];
    __half* s_w  = (__half*)dyn;                       // 42 iof rows x 2048 fp16
    __half* s_hv = (__half*)(dyn + 42 * 4096);         // staged h
    __half* s_mv = (__half*)(dyn + 42 * 4096 + 4096);  // staged m
    __shared__ float s_pre[42];

    const int b = blockIdx.x;
    const int tid = threadIdx.x;
    const int w = tid >> 5, lane = tid & 31;
    const int nu = (b < 124) ? 14 : 13;                // unit j = b + r*148, r < nu
    const bool act = (w < nu);
    const int nbrows = 3 * nu;

    // ---- preload ALL iof weight rows into SMEM ----
    for (int idx = tid; idx < nbrows * 256; idx += NT) {
        int d = idx >> 8, col = idx & 255;
        int g = d / nu, r = d - g * nu;
        int base = (g == 0) ? 0 : (g == 1) ? 2048 : 6144;
        ((uint4*)s_w)[idx] =
            *((const uint4*)(g_Whh + (size_t)(base + b + r * 148) * 2048) + col);
    }

    // ---- per-warp: z-row + Wm-row into registers ----
    uint4 zr[8], mr[8];
    const int j0 = act ? (b + w * 148) : 0;
    float bhz = 0.f, bmu = 0.f, c0 = 0.f;
    if (act) {
        const uint4* pz = (const uint4*)(g_Whh + (size_t)(4096 + j0) * 2048);
        const uint4* pm = (const uint4*)(g_Wmh + (size_t)j0 * 2048);
#pragma unroll
        for (int i = 0; i < 8; i++) {
            zr[i] = __ldg(pz + i * 32 + lane);
            mr[i] = __ldg(pm + i * 32 + lane);
        }
        bhz = bh[4096 + j0];
        bmu = bmv[j0];
    } else {
#pragma unroll
        for (int i = 0; i < 8; i++) { zr[i] = make_uint4(0,0,0,0); mr[i] = make_uint4(0,0,0,0); }
    }

    // ---- per-warp: 3 iof rows + biases ----
    const int d0 = w * 3;
    float bb0 = 0.f, bb1 = 0.f, bb2 = 0.f;
    const bool iof_act = (d0 < nbrows);
    if (iof_act) {
#pragma unroll
        for (int k = 0; k < 3; k++) {
            int d = d0 + k, g = d / nu, r = d - g * nu;
            int base = (g == 0) ? 0 : (g == 1) ? 2048 : 6144;
            float bv = bh[base + b + r * 148];
            if (k == 0) bb0 = bv; else if (k == 1) bb1 = bv; else bb2 = bv;
        }
    }

    // ---- xg prefetch for t=0 ----
    float zx = 0.f, ixv = 0.f, oxv = 0.f, fxv = 0.f, uxv = 0.f;
    if (act) {
        const float* xg = g_xg;
        zx  = __ldg(xg + 4096 + j0);
        ixv = __ldg(xg + j0);
        oxv = __ldg(xg + 2048 + j0);
        fxv = __ldg(xg + 6144 + j0);
        uxv = __ldg(xg + 8192 + j0);
    }
    __syncthreads();

    for (int t = 0; t < T_STEPS; ++t) {
        // ---- stage h: poll tagged words (data arrival IS the sync) ----
        stage_tagged(g_hhT[t & 1], (unsigned short*)s_hv, (unsigned)t, tid);
        __syncthreads();                                 // S1: s_hv ready

        const uint4* hh = (const uint4*)s_hv;

        // ---- Phase A: z dot (register weights, SMEM h); publish m immediately ----
        {
            float ax = 0.f, ay = 0.f;
#pragma unroll
            for (int i = 0; i < 8; i++) mac8(zr[i], hh[i * 32 + lane], ax, ay);
            float z = wsum(ax + ay);
            if (act && lane == 0) {
                float m = sigf(z + bhz + zx) * tanhf_fast(c0);
                __half mh = __float2half_rn(m);
                st_relaxed(&g_mhT[j0],
                           ((unsigned)(t + 1) << 16) | (unsigned)__half_as_ushort(mh));
            }
        }

        // ---- Phase B: 3 iof rows (SMEM weights) -- hides m propagation ----
        if (iof_act) {
            const uint4* q0 = (const uint4*)(s_w + (size_t)(d0 + 0) * 2048);
            const uint4* q1 = (const uint4*)(s_w + (size_t)(d0 + 1) * 2048);
            const uint4* q2 = (const uint4*)(s_w + (size_t)(d0 + 2) * 2048);
            float s0x = 0.f, s0y = 0.f, s1x = 0.f, s1y = 0.f, s2x = 0.f, s2y = 0.f;
#pragma unroll
            for (int i = 0; i < 8; i++) {
                uint4 hv = hh[i * 32 + lane];
                mac8(q0[i * 32 + lane], hv, s0x, s0y);
                mac8(q1[i * 32 + lane], hv, s1x, s1y);
                mac8(q2[i * 32 + lane], hv, s2x, s2y);
            }
            float p0 = wsum(s0x + s0y);
            float p1 = wsum(s1x + s1y);
            float p2 = wsum(s2x + s2y);
            if (lane == 0) {
                s_pre[d0 + 0] = p0 + bb0;
                s_pre[d0 + 1] = p1 + bb1;
                s_pre[d0 + 2] = p2 + bb2;
            }
        }

        // ---- stage m: poll tagged words ----
        stage_tagged(g_mhT, (unsigned short*)s_mv, (unsigned)(t + 1), tid);
        __syncthreads();                                 // S2: s_mv + s_pre ready

        // ---- Phase C: Wm dot (register weights, SMEM m) ----
        float u = 0.f;
        {
            const uint4* mm = (const uint4*)s_mv;
            float ux = 0.f, uy = 0.f;
#pragma unroll
            for (int i = 0; i < 8; i++) mac8(mr[i], mm[i * 32 + lane], ux, uy);
            u = wsum(ux + uy);
        }

        // ---- gates + cell update + publish tagged h ----
        if (act) {
            float i_ = sigf(ixv + s_pre[w]);
            float o_ = sigf(oxv + s_pre[nu + w]);
            float f_ = sigf(fxv + s_pre[2 * nu + w]);
            float uu = tanhf_fast(uxv + u + bmu);
            c0 = i_ * uu + f_ * c0;
            float hn = o_ * tanhf_fast(c0);
            if (lane == 0) {
                if (t == T_STEPS - 1) g_h[j0] = hn;      // fp32 for output
                __half h16 = __float2half_rn(hn);
                st_relaxed(&g_hhT[(t + 1) & 1][j0],
                           ((unsigned)(t + 1) << 16) | (unsigned)__half_as_ushort(h16));
            }
        }

        // ---- xg prefetch for t+1 (overlaps other CTAs' progress) ----
        if (act && t + 1 < T_STEPS) {
            const float* xg = g_xg + (size_t)(t + 1) * NCOL;
            zx  = __ldg(xg + 4096 + j0);
            ixv = __ldg(xg + j0);
            oxv = __ldg(xg + 2048 + j0);
            fxv = __ldg(xg + 6144 + j0);
            uxv = __ldg(xg + 8192 + j0);
        }
        // no end-of-step sync needed: next h-stage polls tags; SMEM hazards
        // are covered by S1/S2 (see proof in commit message)
    }

    // ---- final: one counter barrier so CTA 0 sees everyone's fp32 h ----
    __syncthreads();
    if (tid == 0) red_rel(&g_bar2);
    if (b == 0) {
        if (tid == 0) {
            while (ld_relaxed(&g_bar2) < (unsigned)NCTA) {}
            (void)ld_acq(&g_bar2);
        }
        __syncthreads();
        for (int i = tid; i < MEM; i += NT)
            out[i] = __uint_as_float(ldcg1((const unsigned*)g_h + i));
    }
}

// ---------------- launch ----------------
extern "C" void kernel_launch(void* const* d_in, const int* in_sizes, int n_in,
                              void* d_out, int out_size) {
    const float* inputs = (const float*)d_in[0];
    const float* Wx     = (const float*)d_in[1];
    const float* bx     = (const float*)d_in[2];
    const float* Wh     = (const float*)d_in[3];
    const float* bh     = (const float*)d_in[4];
    const float* Wm     = (const float*)d_in[5];
    const float* bm     = (const float*)d_in[6];
    float* out = (float*)d_out;

    cudaFuncSetAttribute(k_recur, cudaFuncAttributeMaxDynamicSharedMemorySize, DYN_SMEM);

    __half* inh; cudaGetSymbolAddress((void**)&inh, g_inh);
    __half* wxh; cudaGetSymbolAddress((void**)&wxh, g_wxh);

    k_init<<<8, 256>>>();
    k_convert<<<2048, 256>>>(Wh, Wm);
    k_convert2<<<2048, 256>>>(inputs, Wx);
    k_gemm16<<<dim3(NCOL / 128, T_STEPS / 128), 256>>>(inh, wxh, bx);
    k_recur<<<NCTA, NT, DYN_SMEM>>>(bh, bm, out);
}

// round 14
// speedup vs baseline: 2.9242x; 2.9242x over previous
#include <cuda_runtime.h>
#include <cuda_fp16.h>

#define T_STEPS 8192
#define IN_DIM  2048
#define MEM     2048
#define NCOL    10240   // 5*MEM
#define NCTA    148
#define NT      448     // 14 warps

// ---------------- device-global scratch ----------------
__device__ __align__(16) __half g_Whh[(size_t)8192 * 2048];   // fp16 Wh  (33.5 MB)
__device__ __align__(16) __half g_Wmh[(size_t)2048 * 2048];   // fp16 Wm  ( 8.4 MB)
__device__ __align__(16) __half g_inh[(size_t)8192 * 2048];   // fp16 inputs
__device__ __align__(16) __half g_wxh[(size_t)10240 * 2048];  // fp16 Wx
__device__ float  g_xg[(size_t)T_STEPS * NCOL];               // input projections
__device__ __align__(16) float  g_h[2][MEM];                  // fp32 h
__device__ __align__(16) __half g_hh[2][MEM];                 // fp16 h (exchange)
__device__ __align__(16) __half g_mh[MEM];                    // fp16 m (exchange)
__device__ unsigned int g_bar1;
__device__ unsigned int g_bar2;

// ---------------- init (graph-replay safe) ----------------
__global__ void k_init() {
    int i = blockIdx.x * blockDim.x + threadIdx.x;
    if (i == 0) { g_bar1 = 0u; g_bar2 = 0u; }
    if (i < MEM) {
        g_h[0][i] = 0.f; g_h[1][i] = 0.f;
        g_hh[0][i] = __float2half_rn(0.f);
        g_hh[1][i] = __float2half_rn(0.f);
        g_mh[i]    = __float2half_rn(0.f);
    }
}

// ---------------- fp32 -> fp16 conversions (fused: weights + inputs + Wx) ----------------
__global__ void k_convert_all(const float* __restrict__ Wh, const float* __restrict__ Wm,
                              const float* __restrict__ inp, const float* __restrict__ Wx) {
    const int n1 = 8192 * 2048, n2 = 2048 * 2048, n3 = 8192 * 2048, n4 = 10240 * 2048;
    int stride = gridDim.x * blockDim.x;
    int t0 = blockIdx.x * blockDim.x + threadIdx.x;
    for (int i = t0; i < n1; i += stride) g_Whh[i] = __float2half_rn(Wh[i]);
    for (int i = t0; i < n2; i += stride) g_Wmh[i] = __float2half_rn(Wm[i]);
    for (int i = t0; i < n3; i += stride) g_inh[i] = __float2half_rn(inp[i]);
    for (int i = t0; i < n4; i += stride) g_wxh[i] = __float2half_rn(Wx[i]);
}

// ---------------- cp.async helpers ----------------
__device__ __forceinline__ void cp_async16(unsigned smem, const void* gptr) {
    asm volatile("cp.async.cg.shared.global [%0], [%1], 16;" :: "r"(smem), "l"(gptr));
}
__device__ __forceinline__ void cp_commit() { asm volatile("cp.async.commit_group;"); }
__device__ __forceinline__ void cp_wait0()  { asm volatile("cp.async.wait_group 0;"); }

// ---------------- tensor-core GEMM (2-stage cp.async, ONE barrier per iter) ----------------
// C[8192,10240] = A[8192,2048]fp16 * B[10240,2048]^T fp16, fp32 accum.
// 128x128x32 CTA tile, 8 warps (2x4), 64x32 warp tile, mma.m16n8k16.
#define LDT 40   // SMEM stride in halves (conflict-free fragment loads)

__global__ __launch_bounds__(256) void k_gemm16(const __half* __restrict__ A,
                                                const __half* __restrict__ B,
                                                const float* __restrict__ bias) {
    __shared__ __half As[2][128 * LDT];
    __shared__ __half Bs[2][128 * LDT];
    const int tid = threadIdx.x;
    const int warp = tid >> 5, lane = tid & 31;
    const int bm = blockIdx.y * 128, bn = blockIdx.x * 128;
    const int wm = (warp >> 2) * 64, wn = (warp & 3) * 32;
    const int grp = lane >> 2, tig = lane & 3;

    const unsigned sA = (unsigned)__cvta_generic_to_shared(&As[0][0]);
    const unsigned sB = (unsigned)__cvta_generic_to_shared(&Bs[0][0]);
    const unsigned stageBytes = 128 * LDT * 2;

    float acc[4][4][4];
#pragma unroll
    for (int mt = 0; mt < 4; mt++)
#pragma unroll
        for (int nt = 0; nt < 4; nt++)
#pragma unroll
            for (int k = 0; k < 4; k++) acc[mt][nt][k] = 0.f;

    const int row0 = (tid + 0)   >> 2, c40 = (tid + 0)   & 3;
    const int row1 = (tid + 256) >> 2, c41 = (tid + 256) & 3;

    auto issue = [&](int k0, int s) {
        unsigned a0 = sA + s * stageBytes + (row0 * LDT + c40 * 8) * 2;
        unsigned a1 = sA + s * stageBytes + (row1 * LDT + c41 * 8) * 2;
        unsigned b0 = sB + s * stageBytes + (row0 * LDT + c40 * 8) * 2;
        unsigned b1 = sB + s * stageBytes + (row1 * LDT + c41 * 8) * 2;
        cp_async16(a0, A + (size_t)(bm + row0) * IN_DIM + k0 + c40 * 8);
        cp_async16(a1, A + (size_t)(bm + row1) * IN_DIM + k0 + c41 * 8);
        cp_async16(b0, B + (size_t)(bn + row0) * IN_DIM + k0 + c40 * 8);
        cp_async16(b1, B + (size_t)(bn + row1) * IN_DIM + k0 + c41 * 8);
        cp_commit();
    };

    const int NTILE = IN_DIM / 32;   // 64
    issue(0, 0);

    for (int it = 0; it < NTILE; ++it) {
        int s = it & 1;
        // Only ONE group outstanding here (tile it) -> wait_group 0 waits for it.
        cp_wait0();
        __syncthreads();               // buf s ready; all reads of buf s^1 (iter it-1) done
        if (it + 1 < NTILE) issue((it + 1) * 32, s ^ 1);   // overlaps compute below

        const __half* Ab = &As[s][0];
        const __half* Bb = &Bs[s][0];
#pragma unroll
        for (int ks = 0; ks < 32; ks += 16) {
            unsigned bf[4][2];
#pragma unroll
            for (int nt = 0; nt < 4; nt++) {
                const __half* bp = &Bb[(wn + nt * 8 + grp) * LDT + tig * 2 + ks];
                bf[nt][0] = *(const unsigned*)bp;
                bf[nt][1] = *(const unsigned*)(bp + 8);
            }
#pragma unroll
            for (int mt = 0; mt < 4; mt++) {
                const __half* ap = &Ab[(wm + mt * 16 + grp) * LDT + tig * 2 + ks];
                unsigned a0 = *(const unsigned*)ap;
                unsigned a1 = *(const unsigned*)(ap + 8 * LDT);
                unsigned a2 = *(const unsigned*)(ap + 8);
                unsigned a3 = *(const unsigned*)(ap + 8 * LDT + 8);
#pragma unroll
                for (int nt = 0; nt < 4; nt++) {
                    asm volatile(
                        "mma.sync.aligned.m16n8k16.row.col.f32.f16.f16.f32 "
                        "{%0,%1,%2,%3}, {%4,%5,%6,%7}, {%8,%9}, {%0,%1,%2,%3};"
                        : "+f"(acc[mt][nt][0]), "+f"(acc[mt][nt][1]),
                          "+f"(acc[mt][nt][2]), "+f"(acc[mt][nt][3])
                        : "r"(a0), "r"(a1), "r"(a2), "r"(a3),
                          "r"(bf[nt][0]), "r"(bf[nt][1]));
                }
            }
        }
    }

    // ---- epilogue: + bias, fp32 store ----
#pragma unroll
    for (int mt = 0; mt < 4; mt++) {
        int m = bm + wm + mt * 16 + grp;
#pragma unroll
        for (int nt = 0; nt < 4; nt++) {
            int n = bn + wn + nt * 8 + tig * 2;
            float2 bv = *(const float2*)(bias + n);
            float2 o0 = { acc[mt][nt][0] + bv.x, acc[mt][nt][1] + bv.y };
            float2 o1 = { acc[mt][nt][2] + bv.x, acc[mt][nt][3] + bv.y };
            *(float2*)(g_xg + (size_t)m * NCOL + n) = o0;
            *(float2*)(g_xg + (size_t)(m + 8) * NCOL + n) = o1;
        }
    }
}

// ---------------- sync / load / math helpers ----------------
__device__ __forceinline__ unsigned ld_relaxed(const unsigned* p) {
    unsigned v;
    asm volatile("ld.relaxed.gpu.global.u32 %0, [%1];" : "=r"(v) : "l"(p) : "memory");
    return v;
}
__device__ __forceinline__ unsigned ld_acq(const unsigned* p) {
    unsigned v;
    asm volatile("ld.acquire.gpu.global.u32 %0, [%1];" : "=r"(v) : "l"(p) : "memory");
    return v;
}
__device__ __forceinline__ void red_rel(unsigned* p) {
    asm volatile("red.release.gpu.global.add.u32 [%0], 1;" :: "l"(p) : "memory");
}
__device__ __forceinline__ unsigned ldcg1(const unsigned* p) {
    unsigned v;
    asm volatile("ld.global.cg.u32 %0, [%1];" : "=r"(v) : "l"(p) : "memory");
    return v;
}
__device__ __forceinline__ float sigf(float x) { return 1.0f / (1.0f + __expf(-x)); }
// fast tanh via MUFU EX2+RCP (validated R8/R9/R12)
__device__ __forceinline__ float tanhf_fast(float x) {
    return 1.0f - __fdividef(2.0f, 1.0f + __expf(2.0f * x));
}
__device__ __forceinline__ float wsum(float v) {
#pragma unroll
    for (int o = 16; o > 0; o >>= 1) v += __shfl_xor_sync(0xffffffffu, v, o);
    return v;
}
__device__ __forceinline__ __half2 h2u(unsigned u) { return *reinterpret_cast<__half2*>(&u); }

__device__ __forceinline__ void mac8(uint4 wv, uint4 hv, float& ax, float& ay) {
    __half2 p = __hmul2(h2u(wv.x), h2u(hv.x));
    p = __hfma2(h2u(wv.y), h2u(hv.y), p);
    p = __hfma2(h2u(wv.z), h2u(hv.z), p);
    p = __hfma2(h2u(wv.w), h2u(hv.w), p);
    float2 f = __half22float2(p);
    ax += f.x; ay += f.y;
}

// ---------------- persistent recurrent kernel (EXACT R12/R9 structure) ----------------
#define DYN_SMEM (42 * 4096 + 4096 + 4096)

__global__ __launch_bounds__(NT, 1) void k_recur(const float* __restrict__ bh,
                                                 const float* __restrict__ bmv,
                                                 float* __restrict__ out) {
    extern __shared__ __align__(16) unsigned char dyn[];
    __half* s_w  = (__half*)dyn;                       // 42 iof rows x 2048 fp16
    __half* s_hv = (__half*)(dyn + 42 * 4096);         // staged h
    __half* s_mv = (__half*)(dyn + 42 * 4096 + 4096);  // staged m
    __shared__ float s_pre[42];

    const int b = blockIdx.x;
    const int tid = threadIdx.x;
    const int w = tid >> 5, lane = tid & 31;
    const int nu = (b < 124) ? 14 : 13;                // unit j = b + r*148, r < nu
    const bool act = (w < nu);
    const int nbrows = 3 * nu;

    // ---- preload ALL iof weight rows into SMEM ----
    for (int idx = tid; idx < nbrows * 256; idx += NT) {
        int d = idx >> 8, col = idx & 255;
        int g = d / nu, r = d - g * nu;
        int base = (g == 0) ? 0 : (g == 1) ? 2048 : 6144;
        ((uint4*)s_w)[idx] =
            *((const uint4*)(g_Whh + (size_t)(base + b + r * 148) * 2048) + col);
    }

    // ---- per-warp: z-row + Wm-row into registers ----
    uint4 zr[8], mr[8];
    const int j0 = act ? (b + w * 148) : 0;
    float bhz = 0.f, bmu = 0.f, c0 = 0.f;
    if (act) {
        const uint4* pz = (const uint4*)(g_Whh + (size_t)(4096 + j0) * 2048);
        const uint4* pm = (const uint4*)(g_Wmh + (size_t)j0 * 2048);
#pragma unroll
        for (int i = 0; i < 8; i++) {
            zr[i] = __ldg(pz + i * 32 + lane);
            mr[i] = __ldg(pm + i * 32 + lane);
        }
        bhz = bh[4096 + j0];
        bmu = bmv[j0];
    } else {
#pragma unroll
        for (int i = 0; i < 8; i++) { zr[i] = make_uint4(0,0,0,0); mr[i] = make_uint4(0,0,0,0); }
    }

    // ---- per-warp: 3 iof rows + biases ----
    const int d0 = w * 3;
    float bb0 = 0.f, bb1 = 0.f, bb2 = 0.f;
    const bool iof_act = (d0 < nbrows);
    if (iof_act) {
#pragma unroll
        for (int k = 0; k < 3; k++) {
            int d = d0 + k, g = d / nu, r = d - g * nu;
            int base = (g == 0) ? 0 : (g == 1) ? 2048 : 6144;
            float bv = bh[base + b + r * 148];
            if (k == 0) bb0 = bv; else if (k == 1) bb1 = bv; else bb2 = bv;
        }
    }

    // ---- xg prefetch for t=0 ----
    float zx = 0.f, ixv = 0.f, oxv = 0.f, fxv = 0.f, uxv = 0.f;
    if (act) {
        const float* xg = g_xg;
        zx  = __ldg(xg + 4096 + j0);
        ixv = __ldg(xg + j0);
        oxv = __ldg(xg + 2048 + j0);
        fxv = __ldg(xg + 6144 + j0);
        uxv = __ldg(xg + 8192 + j0);
    }
    __syncthreads();

    int cur = 0;
    for (int t = 0; t < T_STEPS; ++t) {
        // ---- wait for all h(t-1) publications (single poller), stage h ----
        if (tid == 0 && t) {
            const unsigned tgt = (unsigned)t * (unsigned)NCTA;
            while (ld_relaxed(&g_bar2) < tgt) {}
            (void)ld_acq(&g_bar2);
        }
        __syncthreads();
        {
            const unsigned* src = (const unsigned*)g_hh[cur];
            unsigned* dst = (unsigned*)s_hv;
#pragma unroll
            for (int i = tid; i < 1024; i += NT) dst[i] = ldcg1(src + i);
        }
        __syncthreads();

        const uint4* hh = (const uint4*)s_hv;

        // ---- Phase A: z dot (register weights, SMEM h) ----
        {
            float ax = 0.f, ay = 0.f;
#pragma unroll
            for (int i = 0; i < 8; i++) mac8(zr[i], hh[i * 32 + lane], ax, ay);
            float z = wsum(ax + ay);
            if (act && lane == 0) {
                float m = sigf(z + bhz + zx) * tanhf_fast(c0);
                g_mh[j0] = __float2half_rn(m);
            }
        }
        __syncthreads();                        // all m stores done
        if (tid == 0) red_rel(&g_bar1);         // publish m (1 release/CTA)

        // ---- Phase B: 3 iof rows (SMEM weights) -- hides bar1 propagation ----
        if (iof_act) {
            const uint4* q0 = (const uint4*)(s_w + (size_t)(d0 + 0) * 2048);
            const uint4* q1 = (const uint4*)(s_w + (size_t)(d0 + 1) * 2048);
            const uint4* q2 = (const uint4*)(s_w + (size_t)(d0 + 2) * 2048);
            float s0x = 0.f, s0y = 0.f, s1x = 0.f, s1y = 0.f, s2x = 0.f, s2y = 0.f;
#pragma unroll
            for (int i = 0; i < 8; i++) {
                uint4 hv = hh[i * 32 + lane];
                mac8(q0[i * 32 + lane], hv, s0x, s0y);
                mac8(q1[i * 32 + lane], hv, s1x, s1y);
                mac8(q2[i * 32 + lane], hv, s2x, s2y);
            }
            float p0 = wsum(s0x + s0y);
            float p1 = wsum(s1x + s1y);
            float p2 = wsum(s2x + s2y);
            if (lane == 0) {
                s_pre[d0 + 0] = p0 + bb0;
                s_pre[d0 + 1] = p1 + bb1;
                s_pre[d0 + 2] = p2 + bb2;
            }
        }

        // ---- bar1 wait (single poller) + stage m into SMEM ----
        if (tid == 0) {
            const unsigned tgt1 = (unsigned)(t + 1) * (unsigned)NCTA;
            while (ld_relaxed(&g_bar1) < tgt1) {}
            (void)ld_acq(&g_bar1);
        }
        __syncthreads();
        {
            const unsigned* src = (const unsigned*)g_mh;
            unsigned* dst = (unsigned*)s_mv;
#pragma unroll
            for (int i = tid; i < 1024; i += NT) dst[i] = ldcg1(src + i);
        }
        __syncthreads();

        // ---- Phase C: Wm dot (register weights, SMEM m) ----
        float u = 0.f;
        {
            const uint4* mm = (const uint4*)s_mv;
            float ux = 0.f, uy = 0.f;
#pragma unroll
            for (int i = 0; i < 8; i++) mac8(mr[i], mm[i * 32 + lane], ux, uy);
            u = wsum(ux + uy);
        }

        // ---- gates + cell update + publish h ----
        if (act) {
            float i_ = sigf(ixv + s_pre[w]);
            float o_ = sigf(oxv + s_pre[nu + w]);
            float f_ = sigf(fxv + s_pre[2 * nu + w]);
            float uu = tanhf_fast(uxv + u + bmu);
            c0 = i_ * uu + f_ * c0;
            float hn = o_ * tanhf_fast(c0);
            if (lane == 0) {
                int nxt = cur ^ 1;
                g_h[nxt][j0]  = hn;
                g_hh[nxt][j0] = __float2half_rn(hn);
            }
        }
        __syncthreads();                        // all h stores done
        if (tid == 0) red_rel(&g_bar2);         // publish h (1 release/CTA)

        // ---- xg prefetch for t+1 (hidden under next bar2 wait) ----
        if (act && t + 1 < T_STEPS) {
            const float* xg = g_xg + (size_t)(t + 1) * NCOL;
            zx  = __ldg(xg + 4096 + j0);
            ixv = __ldg(xg + j0);
            oxv = __ldg(xg + 2048 + j0);
            fxv = __ldg(xg + 6144 + j0);
            uxv = __ldg(xg + 8192 + j0);
        }
        cur ^= 1;
    }

    // ---- output: h_T (CTA 0 copies after all final writes land) ----
    if (b == 0) {
        if (tid == 0) {
            const unsigned tgt = (unsigned)NCTA * (unsigned)T_STEPS;
            while (ld_relaxed(&g_bar2) < tgt) {}
            (void)ld_acq(&g_bar2);
        }
        __syncthreads();
        for (int i = tid; i < MEM; i += NT) out[i] = g_h[T_STEPS & 1][i];
    }
}

// ---------------- launch ----------------
extern "C" void kernel_launch(void* const* d_in, const int* in_sizes, int n_in,
                              void* d_out, int out_size) {
    const float* inputs = (const float*)d_in[0];
    const float* Wx     = (const float*)d_in[1];
    const float* bx     = (const float*)d_in[2];
    const float* Wh     = (const float*)d_in[3];
    const float* bh     = (const float*)d_in[4];
    const float* Wm     = (const float*)d_in[5];
    const float* bm     = (const float*)d_in[6];
    float* out = (float*)d_out;

    cudaFuncSetAttribute(k_recur, cudaFuncAttributeMaxDynamicSharedMemorySize, DYN_SMEM);

    __half* inh; cudaGetSymbolAddress((void**)&inh, g_inh);
    __half* wxh; cudaGetSymbolAddress((void**)&wxh, g_wxh);

    k_init<<<8, 256>>>();
    k_convert_all<<<2048, 256>>>(Wh, Wm, inputs, Wx);
    k_gemm16<<<dim3(NCOL / 128, T_STEPS / 128), 256>>>(inh, wxh, bx);
    k_recur<<<NCTA, NT, DYN_SMEM>>>(bh, bm, out);
}

// round 15
// speedup vs baseline: 3.0015x; 1.0264x over previous
#include <cuda_runtime.h>
#include <cuda_fp16.h>

#define T_STEPS 8192
#define IN_DIM  2048
#define MEM     2048
#define NCOL    10240   // 5*MEM
#define NCTA    148
#define NT      448     // 14 warps

// ---------------- device-global scratch ----------------
__device__ __align__(16) __half g_Whh[(size_t)8192 * 2048];   // fp16 Wh  (33.5 MB)
__device__ __align__(16) __half g_Wmh[(size_t)2048 * 2048];   // fp16 Wm  ( 8.4 MB)
__device__ __align__(16) __half g_inh[(size_t)8192 * 2048];   // fp16 inputs
__device__ __align__(16) __half g_wxh[(size_t)10240 * 2048];  // fp16 Wx
__device__ float  g_xg[(size_t)T_STEPS * NCOL];               // input projections
__device__ __align__(16) float  g_h[2][MEM];                  // fp32 h (final step only)
__device__ __align__(16) __half g_hh[2][MEM];                 // fp16 h (exchange)
__device__ __align__(16) __half g_mh[MEM];                    // fp16 m (exchange)
__device__ unsigned int g_bar1;
__device__ unsigned int g_bar2;

// ---------------- init (graph-replay safe) ----------------
__global__ void k_init() {
    int i = blockIdx.x * blockDim.x + threadIdx.x;
    if (i == 0) { g_bar1 = 0u; g_bar2 = 0u; }
    if (i < MEM) {
        g_h[0][i] = 0.f; g_h[1][i] = 0.f;
        g_hh[0][i] = __float2half_rn(0.f);
        g_hh[1][i] = __float2half_rn(0.f);
        g_mh[i]    = __float2half_rn(0.f);
    }
}

// ---------------- fp32 -> fp16 conversions (two kernels, exactly as R12) ----------------
__global__ void k_convert(const float* __restrict__ Wh, const float* __restrict__ Wm) {
    const int n1 = 8192 * 2048, n2 = 2048 * 2048;
    int stride = gridDim.x * blockDim.x;
    for (int i = blockIdx.x * blockDim.x + threadIdx.x; i < n1; i += stride)
        g_Whh[i] = __float2half_rn(Wh[i]);
    for (int i = blockIdx.x * blockDim.x + threadIdx.x; i < n2; i += stride)
        g_Wmh[i] = __float2half_rn(Wm[i]);
}
__global__ void k_convert2(const float* __restrict__ inp, const float* __restrict__ Wx) {
    const int n1 = 8192 * 2048, n2 = 10240 * 2048;
    int stride = gridDim.x * blockDim.x;
    for (int i = blockIdx.x * blockDim.x + threadIdx.x; i < n1; i += stride)
        g_inh[i] = __float2half_rn(inp[i]);
    for (int i = blockIdx.x * blockDim.x + threadIdx.x; i < n2; i += stride)
        g_wxh[i] = __float2half_rn(Wx[i]);
}

// ---------------- cp.async helpers ----------------
__device__ __forceinline__ void cp_async16(unsigned smem, const void* gptr) {
    asm volatile("cp.async.cg.shared.global [%0], [%1], 16;" :: "r"(smem), "l"(gptr));
}
__device__ __forceinline__ void cp_commit() { asm volatile("cp.async.commit_group;"); }
__device__ __forceinline__ void cp_wait1()  { asm volatile("cp.async.wait_group 1;"); }
__device__ __forceinline__ void cp_wait0()  { asm volatile("cp.async.wait_group 0;"); }

// ---------------- tensor-core GEMM (2-stage cp.async pipeline, EXACT R12 version) ----------------
// C[8192,10240] = A[8192,2048]fp16 * B[10240,2048]^T fp16, fp32 accum.
// 128x128x32 CTA tile, 8 warps (2x4), 64x32 warp tile, mma.m16n8k16.
#define LDT 40   // SMEM stride in halves (conflict-free fragment loads)

__global__ __launch_bounds__(256) void k_gemm16(const __half* __restrict__ A,
                                                const __half* __restrict__ B,
                                                const float* __restrict__ bias) {
    __shared__ __half As[2][128 * LDT];
    __shared__ __half Bs[2][128 * LDT];
    const int tid = threadIdx.x;
    const int warp = tid >> 5, lane = tid & 31;
    const int bm = blockIdx.y * 128, bn = blockIdx.x * 128;
    const int wm = (warp >> 2) * 64, wn = (warp & 3) * 32;
    const int grp = lane >> 2, tig = lane & 3;

    const unsigned sA = (unsigned)__cvta_generic_to_shared(&As[0][0]);
    const unsigned sB = (unsigned)__cvta_generic_to_shared(&Bs[0][0]);
    const unsigned stageBytes = 128 * LDT * 2;

    float acc[4][4][4];
#pragma unroll
    for (int mt = 0; mt < 4; mt++)
#pragma unroll
        for (int nt = 0; nt < 4; nt++)
#pragma unroll
            for (int k = 0; k < 4; k++) acc[mt][nt][k] = 0.f;

    const int row0 = (tid + 0)   >> 2, c40 = (tid + 0)   & 3;
    const int row1 = (tid + 256) >> 2, c41 = (tid + 256) & 3;

    auto issue = [&](int k0, int s) {
        unsigned a0 = sA + s * stageBytes + (row0 * LDT + c40 * 8) * 2;
        unsigned a1 = sA + s * stageBytes + (row1 * LDT + c41 * 8) * 2;
        unsigned b0 = sB + s * stageBytes + (row0 * LDT + c40 * 8) * 2;
        unsigned b1 = sB + s * stageBytes + (row1 * LDT + c41 * 8) * 2;
        cp_async16(a0, A + (size_t)(bm + row0) * IN_DIM + k0 + c40 * 8);
        cp_async16(a1, A + (size_t)(bm + row1) * IN_DIM + k0 + c41 * 8);
        cp_async16(b0, B + (size_t)(bn + row0) * IN_DIM + k0 + c40 * 8);
        cp_async16(b1, B + (size_t)(bn + row1) * IN_DIM + k0 + c41 * 8);
        cp_commit();
    };

    const int NTILE = IN_DIM / 32;   // 64
    issue(0, 0);

    for (int it = 0; it < NTILE; ++it) {
        int s = it & 1;
        if (it + 1 < NTILE) { issue((it + 1) * 32, s ^ 1); cp_wait1(); }
        else                { cp_wait0(); }
        __syncthreads();

        const __half* Ab = &As[s][0];
        const __half* Bb = &Bs[s][0];
#pragma unroll
        for (int ks = 0; ks < 32; ks += 16) {
            unsigned bf[4][2];
#pragma unroll
            for (int nt = 0; nt < 4; nt++) {
                const __half* bp = &Bb[(wn + nt * 8 + grp) * LDT + tig * 2 + ks];
                bf[nt][0] = *(const unsigned*)bp;
                bf[nt][1] = *(const unsigned*)(bp + 8);
            }
#pragma unroll
            for (int mt = 0; mt < 4; mt++) {
                const __half* ap = &Ab[(wm + mt * 16 + grp) * LDT + tig * 2 + ks];
                unsigned a0 = *(const unsigned*)ap;
                unsigned a1 = *(const unsigned*)(ap + 8 * LDT);
                unsigned a2 = *(const unsigned*)(ap + 8);
                unsigned a3 = *(const unsigned*)(ap + 8 * LDT + 8);
#pragma unroll
                for (int nt = 0; nt < 4; nt++) {
                    asm volatile(
                        "mma.sync.aligned.m16n8k16.row.col.f32.f16.f16.f32 "
                        "{%0,%1,%2,%3}, {%4,%5,%6,%7}, {%8,%9}, {%0,%1,%2,%3};"
                        : "+f"(acc[mt][nt][0]), "+f"(acc[mt][nt][1]),
                          "+f"(acc[mt][nt][2]), "+f"(acc[mt][nt][3])
                        : "r"(a0), "r"(a1), "r"(a2), "r"(a3),
                          "r"(bf[nt][0]), "r"(bf[nt][1]));
                }
            }
        }
        __syncthreads();
    }

    // ---- epilogue: + bias, fp32 store ----
#pragma unroll
    for (int mt = 0; mt < 4; mt++) {
        int m = bm + wm + mt * 16 + grp;
#pragma unroll
        for (int nt = 0; nt < 4; nt++) {
            int n = bn + wn + nt * 8 + tig * 2;
            float2 bv = *(const float2*)(bias + n);
            float2 o0 = { acc[mt][nt][0] + bv.x, acc[mt][nt][1] + bv.y };
            float2 o1 = { acc[mt][nt][2] + bv.x, acc[mt][nt][3] + bv.y };
            *(float2*)(g_xg + (size_t)m * NCOL + n) = o0;
            *(float2*)(g_xg + (size_t)(m + 8) * NCOL + n) = o1;
        }
    }
}

// ---------------- sync / load / math helpers ----------------
__device__ __forceinline__ unsigned ld_relaxed(const unsigned* p) {
    unsigned v;
    asm volatile("ld.relaxed.gpu.global.u32 %0, [%1];" : "=r"(v) : "l"(p) : "memory");
    return v;
}
__device__ __forceinline__ unsigned ld_acq(const unsigned* p) {
    unsigned v;
    asm volatile("ld.acquire.gpu.global.u32 %0, [%1];" : "=r"(v) : "l"(p) : "memory");
    return v;
}
__device__ __forceinline__ void red_rel(unsigned* p) {
    asm volatile("red.release.gpu.global.add.u32 [%0], 1;" :: "l"(p) : "memory");
}
__device__ __forceinline__ unsigned ldcg1(const unsigned* p) {
    unsigned v;
    asm volatile("ld.global.cg.u32 %0, [%1];" : "=r"(v) : "l"(p) : "memory");
    return v;
}
__device__ __forceinline__ float sigf(float x) { return 1.0f / (1.0f + __expf(-x)); }
// fast tanh via MUFU EX2+RCP (validated R8/R9/R12)
__device__ __forceinline__ float tanhf_fast(float x) {
    return 1.0f - __fdividef(2.0f, 1.0f + __expf(2.0f * x));
}
__device__ __forceinline__ float wsum(float v) {
#pragma unroll
    for (int o = 16; o > 0; o >>= 1) v += __shfl_xor_sync(0xffffffffu, v, o);
    return v;
}
__device__ __forceinline__ __half2 h2u(unsigned u) { return *reinterpret_cast<__half2*>(&u); }

__device__ __forceinline__ void mac8(uint4 wv, uint4 hv, float& ax, float& ay) {
    __half2 p = __hmul2(h2u(wv.x), h2u(hv.x));
    p = __hfma2(h2u(wv.y), h2u(hv.y), p);
    p = __hfma2(h2u(wv.z), h2u(hv.z), p);
    p = __hfma2(h2u(wv.w), h2u(hv.w), p);
    float2 f = __half22float2(p);
    ax += f.x; ay += f.y;
}

// ---------------- persistent recurrent kernel (R12 structure; fp32 h stored only at final step) ----------------
#define DYN_SMEM (42 * 4096 + 4096 + 4096)

__global__ __launch_bounds__(NT, 1) void k_recur(const float* __restrict__ bh,
                                                 const float* __restrict__ bmv,
                                                 float* __restrict__ out) {
    extern __shared__ __align__(16) unsigned char dyn[];
    __half* s_w  = (__half*)dyn;                       // 42 iof rows x 2048 fp16
    __half* s_hv = (__half*)(dyn + 42 * 4096);         // staged h
    __half* s_mv = (__half*)(dyn + 42 * 4096 + 4096);  // staged m
    __shared__ float s_pre[42];

    const int b = blockIdx.x;
    const int tid = threadIdx.x;
    const int w = tid >> 5, lane = tid & 31;
    const int nu = (b < 124) ? 14 : 13;                // unit j = b + r*148, r < nu
    const bool act = (w < nu);
    const int nbrows = 3 * nu;

    // ---- preload ALL iof weight rows into SMEM ----
    for (int idx = tid; idx < nbrows * 256; idx += NT) {
        int d = idx >> 8, col = idx & 255;
        int g = d / nu, r = d - g * nu;
        int base = (g == 0) ? 0 : (g == 1) ? 2048 : 6144;
        ((uint4*)s_w)[idx] =
            *((const uint4*)(g_Whh + (size_t)(base + b + r * 148) * 2048) + col);
    }

    // ---- per-warp: z-row + Wm-row into registers ----
    uint4 zr[8], mr[8];
    const int j0 = act ? (b + w * 148) : 0;
    float bhz = 0.f, bmu = 0.f, c0 = 0.f;
    if (act) {
        const uint4* pz = (const uint4*)(g_Whh + (size_t)(4096 + j0) * 2048);
        const uint4* pm = (const uint4*)(g_Wmh + (size_t)j0 * 2048);
#pragma unroll
        for (int i = 0; i < 8; i++) {
            zr[i] = __ldg(pz + i * 32 + lane);
            mr[i] = __ldg(pm + i * 32 + lane);
        }
        bhz = bh[4096 + j0];
        bmu = bmv[j0];
    } else {
#pragma unroll
        for (int i = 0; i < 8; i++) { zr[i] = make_uint4(0,0,0,0); mr[i] = make_uint4(0,0,0,0); }
    }

    // ---- per-warp: 3 iof rows + biases ----
    const int d0 = w * 3;
    float bb0 = 0.f, bb1 = 0.f, bb2 = 0.f;
    const bool iof_act = (d0 < nbrows);
    if (iof_act) {
#pragma unroll
        for (int k = 0; k < 3; k++) {
            int d = d0 + k, g = d / nu, r = d - g * nu;
            int base = (g == 0) ? 0 : (g == 1) ? 2048 : 6144;
            float bv = bh[base + b + r * 148];
            if (k == 0) bb0 = bv; else if (k == 1) bb1 = bv; else bb2 = bv;
        }
    }

    // ---- xg prefetch for t=0 ----
    float zx = 0.f, ixv = 0.f, oxv = 0.f, fxv = 0.f, uxv = 0.f;
    if (act) {
        const float* xg = g_xg;
        zx  = __ldg(xg + 4096 + j0);
        ixv = __ldg(xg + j0);
        oxv = __ldg(xg + 2048 + j0);
        fxv = __ldg(xg + 6144 + j0);
        uxv = __ldg(xg + 8192 + j0);
    }
    __syncthreads();

    int cur = 0;
    for (int t = 0; t < T_STEPS; ++t) {
        // ---- wait for all h(t-1) publications (single poller), stage h ----
        if (tid == 0 && t) {
            const unsigned tgt = (unsigned)t * (unsigned)NCTA;
            while (ld_relaxed(&g_bar2) < tgt) {}
            (void)ld_acq(&g_bar2);
        }
        __syncthreads();
        {
            const unsigned* src = (const unsigned*)g_hh[cur];
            unsigned* dst = (unsigned*)s_hv;
#pragma unroll
            for (int i = tid; i < 1024; i += NT) dst[i] = ldcg1(src + i);
        }
        __syncthreads();

        const uint4* hh = (const uint4*)s_hv;

        // ---- Phase A: z dot (register weights, SMEM h) ----
        {
            float ax = 0.f, ay = 0.f;
#pragma unroll
            for (int i = 0; i < 8; i++) mac8(zr[i], hh[i * 32 + lane], ax, ay);
            float z = wsum(ax + ay);
            if (act && lane == 0) {
                float m = sigf(z + bhz + zx) * tanhf_fast(c0);
                g_mh[j0] = __float2half_rn(m);
            }
        }
        __syncthreads();                        // all m stores done
        if (tid == 0) red_rel(&g_bar1);         // publish m (1 release/CTA)

        // ---- Phase B: 3 iof rows (SMEM weights) -- hides bar1 propagation ----
        if (iof_act) {
            const uint4* q0 = (const uint4*)(s_w + (size_t)(d0 + 0) * 2048);
            const uint4* q1 = (const uint4*)(s_w + (size_t)(d0 + 1) * 2048);
            const uint4* q2 = (const uint4*)(s_w + (size_t)(d0 + 2) * 2048);
            float s0x = 0.f, s0y = 0.f, s1x = 0.f, s1y = 0.f, s2x = 0.f, s2y = 0.f;
#pragma unroll
            for (int i = 0; i < 8; i++) {
                uint4 hv = hh[i * 32 + lane];
                mac8(q0[i * 32 + lane], hv, s0x, s0y);
                mac8(q1[i * 32 + lane], hv, s1x, s1y);
                mac8(q2[i * 32 + lane], hv, s2x, s2y);
            }
            float p0 = wsum(s0x + s0y);
            float p1 = wsum(s1x + s1y);
            float p2 = wsum(s2x + s2y);
            if (lane == 0) {
                s_pre[d0 + 0] = p0 + bb0;
                s_pre[d0 + 1] = p1 + bb1;
                s_pre[d0 + 2] = p2 + bb2;
            }
        }

        // ---- bar1 wait (single poller) + stage m into SMEM ----
        if (tid == 0) {
            const unsigned tgt1 = (unsigned)(t + 1) * (unsigned)NCTA;
            while (ld_relaxed(&g_bar1) < tgt1) {}
            (void)ld_acq(&g_bar1);
        }
        __syncthreads();
        {
            const unsigned* src = (const unsigned*)g_mh;
            unsigned* dst = (unsigned*)s_mv;
#pragma unroll
            for (int i = tid; i < 1024; i += NT) dst[i] = ldcg1(src + i);
        }
        __syncthreads();

        // ---- Phase C: Wm dot (register weights, SMEM m) ----
        float u = 0.f;
        {
            const uint4* mm = (const uint4*)s_mv;
            float ux = 0.f, uy = 0.f;
#pragma unroll
            for (int i = 0; i < 8; i++) mac8(mr[i], mm[i * 32 + lane], ux, uy);
            u = wsum(ux + uy);
        }

        // ---- gates + cell update + publish h ----
        if (act) {
            float i_ = sigf(ixv + s_pre[w]);
            float o_ = sigf(oxv + s_pre[nu + w]);
            float f_ = sigf(fxv + s_pre[2 * nu + w]);
            float uu = tanhf_fast(uxv + u + bmu);
            c0 = i_ * uu + f_ * c0;
            float hn = o_ * tanhf_fast(c0);
            if (lane == 0) {
                int nxt = cur ^ 1;
                g_hh[nxt][j0] = __float2half_rn(hn);
                if (t == T_STEPS - 1) g_h[nxt][j0] = hn;   // fp32 only at final step
            }
        }
        __syncthreads();                        // all h stores done
        if (tid == 0) red_rel(&g_bar2);         // publish h (1 release/CTA)

        // ---- xg prefetch for t+1 (hidden under next bar2 wait) ----
        if (act && t + 1 < T_STEPS) {
            const float* xg = g_xg + (size_t)(t + 1) * NCOL;
            zx  = __ldg(xg + 4096 + j0);
            ixv = __ldg(xg + j0);
            oxv = __ldg(xg + 2048 + j0);
            fxv = __ldg(xg + 6144 + j0);
            uxv = __ldg(xg + 8192 + j0);
        }
        cur ^= 1;
    }

    // ---- output: h_T (CTA 0 copies after all final writes land) ----
    if (b == 0) {
        if (tid == 0) {
            const unsigned tgt = (unsigned)NCTA * (unsigned)T_STEPS;
            while (ld_relaxed(&g_bar2) < tgt) {}
            (void)ld_acq(&g_bar2);
        }
        __syncthreads();
        for (int i = tid; i < MEM; i += NT)
            out[i] = __uint_as_float(ldcg1((const unsigned*)g_h[T_STEPS & 1] + i));
    }
}

// ---------------- launch ----------------
extern "C" void kernel_launch(void* const* d_in, const int* in_sizes, int n_in,
                              void* d_out, int out_size) {
    const float* inputs = (const float*)d_in[0];
    const float* Wx     = (const float*)d_in[1];
    const float* bx     = (const float*)d_in[2];
    const float* Wh     = (const float*)d_in[3];
    const float* bh     = (const float*)d_in[4];
    const float* Wm     = (const float*)d_in[5];
    const float* bm     = (const float*)d_in[6];
    float* out = (float*)d_out;

    cudaFuncSetAttribute(k_recur, cudaFuncAttributeMaxDynamicSharedMemorySize, DYN_SMEM);

    __half* inh; cudaGetSymbolAddress((void**)&inh, g_inh);
    __half* wxh; cudaGetSymbolAddress((void**)&wxh, g_wxh);

    k_init<<<8, 256>>>();
    k_convert<<<2048, 256>>>(Wh, Wm);
    k_convert2<<<2048, 256>>>(inputs, Wx);
    k_gemm16<<<dim3(NCOL / 128, T_STEPS / 128), 256>>>(inh, wxh, bx);
    k_recur<<<NCTA, NT, DYN_SMEM>>>(bh, bm, out);
}

// round 16
// speedup vs baseline: 3.0462x; 1.0149x over previous
#include <cuda_runtime.h>
#include <cuda_fp16.h>

#define T_STEPS 8192
#define IN_DIM  2048
#define MEM     2048
#define NCOL    10240   // 5*MEM
#define NCTA    148
#define NT      448     // 14 warps

// ---------------- device-global scratch ----------------
__device__ __align__(16) __half g_Whh[(size_t)8192 * 2048];   // fp16 Wh  (33.5 MB)
__device__ __align__(16) __half g_Wmh[(size_t)2048 * 2048];   // fp16 Wm  ( 8.4 MB)
__device__ __align__(16) __half g_inh[(size_t)8192 * 2048];   // fp16 inputs
__device__ __align__(16) __half g_wxh[(size_t)10240 * 2048];  // fp16 Wx
__device__ float  g_xg[(size_t)T_STEPS * NCOL];               // input projections
__device__ __align__(16) float  g_h[2][MEM];                  // fp32 h
__device__ __align__(16) __half g_hh[2][MEM];                 // fp16 h (exchange)
__device__ __align__(16) __half g_mh[MEM];                    // fp16 m (exchange)
__device__ unsigned int g_bar1;
__device__ unsigned int g_bar2;

// ---------------- init (graph-replay safe) ----------------
__global__ void k_init() {
    int i = blockIdx.x * blockDim.x + threadIdx.x;
    if (i == 0) { g_bar1 = 0u; g_bar2 = 0u; }
    if (i < MEM) {
        g_h[0][i] = 0.f; g_h[1][i] = 0.f;
        g_hh[0][i] = __float2half_rn(0.f);
        g_hh[1][i] = __float2half_rn(0.f);
        g_mh[i]    = __float2half_rn(0.f);
    }
}

// ---------------- fp32 -> fp16 conversions ----------------
__global__ void k_convert(const float* __restrict__ Wh, const float* __restrict__ Wm) {
    const int n1 = 8192 * 2048, n2 = 2048 * 2048;
    int stride = gridDim.x * blockDim.x;
    for (int i = blockIdx.x * blockDim.x + threadIdx.x; i < n1; i += stride)
        g_Whh[i] = __float2half_rn(Wh[i]);
    for (int i = blockIdx.x * blockDim.x + threadIdx.x; i < n2; i += stride)
        g_Wmh[i] = __float2half_rn(Wm[i]);
}
__global__ void k_convert2(const float* __restrict__ inp, const float* __restrict__ Wx) {
    const int n1 = 8192 * 2048, n2 = 10240 * 2048;
    int stride = gridDim.x * blockDim.x;
    for (int i = blockIdx.x * blockDim.x + threadIdx.x; i < n1; i += stride)
        g_inh[i] = __float2half_rn(inp[i]);
    for (int i = blockIdx.x * blockDim.x + threadIdx.x; i < n2; i += stride)
        g_wxh[i] = __float2half_rn(Wx[i]);
}

// ---------------- cp.async helpers ----------------
__device__ __forceinline__ void cp_async16(unsigned smem, const void* gptr) {
    asm volatile("cp.async.cg.shared.global [%0], [%1], 16;" :: "r"(smem), "l"(gptr));
}
__device__ __forceinline__ void cp_commit() { asm volatile("cp.async.commit_group;"); }
__device__ __forceinline__ void cp_wait1()  { asm volatile("cp.async.wait_group 1;"); }
__device__ __forceinline__ void cp_wait0()  { asm volatile("cp.async.wait_group 0;"); }

// ---------------- tensor-core GEMM (2-stage cp.async pipeline, validated R10/R12) ----------------
// C[8192,10240] = A[8192,2048]fp16 * B[10240,2048]^T fp16, fp32 accum.
// 128x128x32 CTA tile, 8 warps (2x4), 64x32 warp tile, mma.m16n8k16.
#define LDT 40   // SMEM stride in halves (conflict-free fragment loads)

__global__ __launch_bounds__(256) void k_gemm16(const __half* __restrict__ A,
                                                const __half* __restrict__ B,
                                                const float* __restrict__ bias) {
    __shared__ __half As[2][128 * LDT];
    __shared__ __half Bs[2][128 * LDT];
    const int tid = threadIdx.x;
    const int warp = tid >> 5, lane = tid & 31;
    const int bm = blockIdx.y * 128, bn = blockIdx.x * 128;
    const int wm = (warp >> 2) * 64, wn = (warp & 3) * 32;
    const int grp = lane >> 2, tig = lane & 3;

    const unsigned sA = (unsigned)__cvta_generic_to_shared(&As[0][0]);
    const unsigned sB = (unsigned)__cvta_generic_to_shared(&Bs[0][0]);
    const unsigned stageBytes = 128 * LDT * 2;

    float acc[4][4][4];
#pragma unroll
    for (int mt = 0; mt < 4; mt++)
#pragma unroll
        for (int nt = 0; nt < 4; nt++)
#pragma unroll
            for (int k = 0; k < 4; k++) acc[mt][nt][k] = 0.f;

    const int row0 = (tid + 0)   >> 2, c40 = (tid + 0)   & 3;
    const int row1 = (tid + 256) >> 2, c41 = (tid + 256) & 3;

    auto issue = [&](int k0, int s) {
        unsigned a0 = sA + s * stageBytes + (row0 * LDT + c40 * 8) * 2;
        unsigned a1 = sA + s * stageBytes + (row1 * LDT + c41 * 8) * 2;
        unsigned b0 = sB + s * stageBytes + (row0 * LDT + c40 * 8) * 2;
        unsigned b1 = sB + s * stageBytes + (row1 * LDT + c41 * 8) * 2;
        cp_async16(a0, A + (size_t)(bm + row0) * IN_DIM + k0 + c40 * 8);
        cp_async16(a1, A + (size_t)(bm + row1) * IN_DIM + k0 + c41 * 8);
        cp_async16(b0, B + (size_t)(bn + row0) * IN_DIM + k0 + c40 * 8);
        cp_async16(b1, B + (size_t)(bn + row1) * IN_DIM + k0 + c41 * 8);
        cp_commit();
    };

    const int NTILE = IN_DIM / 32;   // 64
    issue(0, 0);

    for (int it = 0; it < NTILE; ++it) {
        int s = it & 1;
        if (it + 1 < NTILE) { issue((it + 1) * 32, s ^ 1); cp_wait1(); }
        else                { cp_wait0(); }
        __syncthreads();

        const __half* Ab = &As[s][0];
        const __half* Bb = &Bs[s][0];
#pragma unroll
        for (int ks = 0; ks < 32; ks += 16) {
            unsigned bf[4][2];
#pragma unroll
            for (int nt = 0; nt < 4; nt++) {
                const __half* bp = &Bb[(wn + nt * 8 + grp) * LDT + tig * 2 + ks];
                bf[nt][0] = *(const unsigned*)bp;
                bf[nt][1] = *(const unsigned*)(bp + 8);
            }
#pragma unroll
            for (int mt = 0; mt < 4; mt++) {
                const __half* ap = &Ab[(wm + mt * 16 + grp) * LDT + tig * 2 + ks];
                unsigned a0 = *(const unsigned*)ap;
                unsigned a1 = *(const unsigned*)(ap + 8 * LDT);
                unsigned a2 = *(const unsigned*)(ap + 8);
                unsigned a3 = *(const unsigned*)(ap + 8 * LDT + 8);
#pragma unroll
                for (int nt = 0; nt < 4; nt++) {
                    asm volatile(
                        "mma.sync.aligned.m16n8k16.row.col.f32.f16.f16.f32 "
                        "{%0,%1,%2,%3}, {%4,%5,%6,%7}, {%8,%9}, {%0,%1,%2,%3};"
                        : "+f"(acc[mt][nt][0]), "+f"(acc[mt][nt][1]),
                          "+f"(acc[mt][nt][2]), "+f"(acc[mt][nt][3])
                        : "r"(a0), "r"(a1), "r"(a2), "r"(a3),
                          "r"(bf[nt][0]), "r"(bf[nt][1]));
                }
            }
        }
        __syncthreads();
    }

    // ---- epilogue: + bias, fp32 store ----
#pragma unroll
    for (int mt = 0; mt < 4; mt++) {
        int m = bm + wm + mt * 16 + grp;
#pragma unroll
        for (int nt = 0; nt < 4; nt++) {
            int n = bn + wn + nt * 8 + tig * 2;
            float2 bv = *(const float2*)(bias + n);
            float2 o0 = { acc[mt][nt][0] + bv.x, acc[mt][nt][1] + bv.y };
            float2 o1 = { acc[mt][nt][2] + bv.x, acc[mt][nt][3] + bv.y };
            *(float2*)(g_xg + (size_t)m * NCOL + n) = o0;
            *(float2*)(g_xg + (size_t)(m + 8) * NCOL + n) = o1;
        }
    }
}

// ---------------- sync / load / math helpers ----------------
__device__ __forceinline__ unsigned ld_relaxed(const unsigned* p) {
    unsigned v;
    asm volatile("ld.relaxed.gpu.global.u32 %0, [%1];" : "=r"(v) : "l"(p) : "memory");
    return v;
}
__device__ __forceinline__ unsigned ld_acq(const unsigned* p) {
    unsigned v;
    asm volatile("ld.acquire.gpu.global.u32 %0, [%1];" : "=r"(v) : "l"(p) : "memory");
    return v;
}
__device__ __forceinline__ void red_rel(unsigned* p) {
    asm volatile("red.release.gpu.global.add.u32 [%0], 1;" :: "l"(p) : "memory");
}
__device__ __forceinline__ unsigned ldcg1(const unsigned* p) {
    unsigned v;
    asm volatile("ld.global.cg.u32 %0, [%1];" : "=r"(v) : "l"(p) : "memory");
    return v;
}
__device__ __forceinline__ float sigf(float x) { return 1.0f / (1.0f + __expf(-x)); }
// fast tanh via MUFU EX2+RCP (validated R8/R9/R12)
__device__ __forceinline__ float tanhf_fast(float x) {
    return 1.0f - __fdividef(2.0f, 1.0f + __expf(2.0f * x));
}
__device__ __forceinline__ float wsum(float v) {
#pragma unroll
    for (int o = 16; o > 0; o >>= 1) v += __shfl_xor_sync(0xffffffffu, v, o);
    return v;
}
__device__ __forceinline__ __half2 h2u(unsigned u) { return *reinterpret_cast<__half2*>(&u); }

__device__ __forceinline__ void mac8(uint4 wv, uint4 hv, float& ax, float& ay) {
    __half2 p = __hmul2(h2u(wv.x), h2u(hv.x));
    p = __hfma2(h2u(wv.y), h2u(hv.y), p);
    p = __hfma2(h2u(wv.z), h2u(hv.z), p);
    p = __hfma2(h2u(wv.w), h2u(hv.w), p);
    float2 f = __half22float2(p);
    ax += f.x; ay += f.y;
}

// ---------------- persistent recurrent kernel (R12: validated optimum) ----------------
#define DYN_SMEM (42 * 4096 + 4096 + 4096)

__global__ __launch_bounds__(NT, 1) void k_recur(const float* __restrict__ bh,
                                                 const float* __restrict__ bmv,
                                                 float* __restrict__ out) {
    extern __shared__ __align__(16) unsigned char dyn[];
    __half* s_w  = (__half*)dyn;                       // 42 iof rows x 2048 fp16
    __half* s_hv = (__half*)(dyn + 42 * 4096);         // staged h
    __half* s_mv = (__half*)(dyn + 42 * 4096 + 4096);  // staged m
    __shared__ float s_pre[42];

    const int b = blockIdx.x;
    const int tid = threadIdx.x;
    const int w = tid >> 5, lane = tid & 31;
    const int nu = (b < 124) ? 14 : 13;                // unit j = b + r*148, r < nu
    const bool act = (w < nu);
    const int nbrows = 3 * nu;

    // ---- preload ALL iof weight rows into SMEM ----
    for (int idx = tid; idx < nbrows * 256; idx += NT) {
        int d = idx >> 8, col = idx & 255;
        int g = d / nu, r = d - g * nu;
        int base = (g == 0) ? 0 : (g == 1) ? 2048 : 6144;
        ((uint4*)s_w)[idx] =
            *((const uint4*)(g_Whh + (size_t)(base + b + r * 148) * 2048) + col);
    }

    // ---- per-warp: z-row + Wm-row into registers ----
    uint4 zr[8], mr[8];
    const int j0 = act ? (b + w * 148) : 0;
    float bhz = 0.f, bmu = 0.f, c0 = 0.f;
    if (act) {
        const uint4* pz = (const uint4*)(g_Whh + (size_t)(4096 + j0) * 2048);
        const uint4* pm = (const uint4*)(g_Wmh + (size_t)j0 * 2048);
#pragma unroll
        for (int i = 0; i < 8; i++) {
            zr[i] = __ldg(pz + i * 32 + lane);
            mr[i] = __ldg(pm + i * 32 + lane);
        }
        bhz = bh[4096 + j0];
        bmu = bmv[j0];
    } else {
#pragma unroll
        for (int i = 0; i < 8; i++) { zr[i] = make_uint4(0,0,0,0); mr[i] = make_uint4(0,0,0,0); }
    }

    // ---- per-warp: 3 iof rows + biases ----
    const int d0 = w * 3;
    float bb0 = 0.f, bb1 = 0.f, bb2 = 0.f;
    const bool iof_act = (d0 < nbrows);
    if (iof_act) {
#pragma unroll
        for (int k = 0; k < 3; k++) {
            int d = d0 + k, g = d / nu, r = d - g * nu;
            int base = (g == 0) ? 0 : (g == 1) ? 2048 : 6144;
            float bv = bh[base + b + r * 148];
            if (k == 0) bb0 = bv; else if (k == 1) bb1 = bv; else bb2 = bv;
        }
    }

    // ---- xg prefetch for t=0 ----
    float zx = 0.f, ixv = 0.f, oxv = 0.f, fxv = 0.f, uxv = 0.f;
    if (act) {
        const float* xg = g_xg;
        zx  = __ldg(xg + 4096 + j0);
        ixv = __ldg(xg + j0);
        oxv = __ldg(xg + 2048 + j0);
        fxv = __ldg(xg + 6144 + j0);
        uxv = __ldg(xg + 8192 + j0);
    }
    __syncthreads();

    int cur = 0;
    for (int t = 0; t < T_STEPS; ++t) {
        // ---- wait for all h(t-1) publications (single poller), stage h ----
        if (tid == 0 && t) {
            const unsigned tgt = (unsigned)t * (unsigned)NCTA;
            while (ld_relaxed(&g_bar2) < tgt) {}
            (void)ld_acq(&g_bar2);
        }
        __syncthreads();
        {
            const unsigned* src = (const unsigned*)g_hh[cur];
            unsigned* dst = (unsigned*)s_hv;
#pragma unroll
            for (int i = tid; i < 1024; i += NT) dst[i] = ldcg1(src + i);
        }
        __syncthreads();

        const uint4* hh = (const uint4*)s_hv;

        // ---- Phase A: z dot (register weights, SMEM h) ----
        {
            float ax = 0.f, ay = 0.f;
#pragma unroll
            for (int i = 0; i < 8; i++) mac8(zr[i], hh[i * 32 + lane], ax, ay);
            float z = wsum(ax + ay);
            if (act && lane == 0) {
                float m = sigf(z + bhz + zx) * tanhf_fast(c0);
                g_mh[j0] = __float2half_rn(m);
            }
        }
        __syncthreads();                        // all m stores done
        if (tid == 0) red_rel(&g_bar1);         // publish m (1 release/CTA)

        // ---- Phase B: 3 iof rows (SMEM weights) -- hides bar1 propagation ----
        if (iof_act) {
            const uint4* q0 = (const uint4*)(s_w + (size_t)(d0 + 0) * 2048);
            const uint4* q1 = (const uint4*)(s_w + (size_t)(d0 + 1) * 2048);
            const uint4* q2 = (const uint4*)(s_w + (size_t)(d0 + 2) * 2048);
            float s0x = 0.f, s0y = 0.f, s1x = 0.f, s1y = 0.f, s2x = 0.f, s2y = 0.f;
#pragma unroll
            for (int i = 0; i < 8; i++) {
                uint4 hv = hh[i * 32 + lane];
                mac8(q0[i * 32 + lane], hv, s0x, s0y);
                mac8(q1[i * 32 + lane], hv, s1x, s1y);
                mac8(q2[i * 32 + lane], hv, s2x, s2y);
            }
            float p0 = wsum(s0x + s0y);
            float p1 = wsum(s1x + s1y);
            float p2 = wsum(s2x + s2y);
            if (lane == 0) {
                s_pre[d0 + 0] = p0 + bb0;
                s_pre[d0 + 1] = p1 + bb1;
                s_pre[d0 + 2] = p2 + bb2;
            }
        }

        // ---- bar1 wait (single poller) + stage m into SMEM ----
        if (tid == 0) {
            const unsigned tgt1 = (unsigned)(t + 1) * (unsigned)NCTA;
            while (ld_relaxed(&g_bar1) < tgt1) {}
            (void)ld_acq(&g_bar1);
        }
        __syncthreads();
        {
            const unsigned* src = (const unsigned*)g_mh;
            unsigned* dst = (unsigned*)s_mv;
#pragma unroll
            for (int i = tid; i < 1024; i += NT) dst[i] = ldcg1(src + i);
        }
        __syncthreads();

        // ---- Phase C: Wm dot (register weights, SMEM m) ----
        float u = 0.f;
        {
            const uint4* mm = (const uint4*)s_mv;
            float ux = 0.f, uy = 0.f;
#pragma unroll
            for (int i = 0; i < 8; i++) mac8(mr[i], mm[i * 32 + lane], ux, uy);
            u = wsum(ux + uy);
        }

        // ---- gates + cell update + publish h ----
        if (act) {
            float i_ = sigf(ixv + s_pre[w]);
            float o_ = sigf(oxv + s_pre[nu + w]);
            float f_ = sigf(fxv + s_pre[2 * nu + w]);
            float uu = tanhf_fast(uxv + u + bmu);
            c0 = i_ * uu + f_ * c0;
            float hn = o_ * tanhf_fast(c0);
            if (lane == 0) {
                int nxt = cur ^ 1;
                g_h[nxt][j0]  = hn;
                g_hh[nxt][j0] = __float2half_rn(hn);
            }
        }
        __syncthreads();                        // all h stores done
        if (tid == 0) red_rel(&g_bar2);         // publish h (1 release/CTA)

        // ---- xg prefetch for t+1 (hidden under next bar2 wait) ----
        if (act && t + 1 < T_STEPS) {
            const float* xg = g_xg + (size_t)(t + 1) * NCOL;
            zx  = __ldg(xg + 4096 + j0);
            ixv = __ldg(xg + j0);
            oxv = __ldg(xg + 2048 + j0);
            fxv = __ldg(xg + 6144 + j0);
            uxv = __ldg(xg + 8192 + j0);
        }
        cur ^= 1;
    }

    // ---- output: h_T (CTA 0 copies after all final writes land) ----
    if (b == 0) {
        if (tid == 0) {
            const unsigned tgt = (unsigned)NCTA * (unsigned)T_STEPS;
            while (ld_relaxed(&g_bar2) < tgt) {}
            (void)ld_acq(&g_bar2);
        }
        __syncthreads();
        for (int i = tid; i < MEM; i += NT) out[i] = g_h[T_STEPS & 1][i];
    }
}

// ---------------- launch ----------------
extern "C" void kernel_launch(void* const* d_in, const int* in_sizes, int n_in,
                              void* d_out, int out_size) {
    const float* inputs = (const float*)d_in[0];
    const float* Wx     = (const float*)d_in[1];
    const float* bx     = (const float*)d_in[2];
    const float* Wh     = (const float*)d_in[3];
    const float* bh     = (const float*)d_in[4];
    const float* Wm     = (const float*)d_in[5];
    const float* bm     = (const float*)d_in[6];
    float* out = (float*)d_out;

    cudaFuncSetAttribute(k_recur, cudaFuncAttributeMaxDynamicSharedMemorySize, DYN_SMEM);

    __half* inh; cudaGetSymbolAddress((void**)&inh, g_inh);
    __half* wxh; cudaGetSymbolAddress((void**)&wxh, g_wxh);

    k_init<<<8, 256>>>();
    k_convert<<<2048, 256>>>(Wh, Wm);
    k_convert2<<<2048, 256>>>(inputs, Wx);
    k_gemm16<<<dim3(NCOL / 128, T_STEPS / 128), 256>>>(inh, wxh, bx);
    k_recur<<<NCTA, NT, DYN_SMEM>>>(bh, bm, out);
}

// round 17
// speedup vs baseline: 3.0538x; 1.0025x over previous
#include <cuda_runtime.h>
#include <cuda_fp16.h>

#define T_STEPS 8192
#define IN_DIM  2048
#define MEM     2048
#define NCOL    10240   // 5*MEM
#define NCTA    148
#define NT      448     // 14 warps

// ---------------- device-global scratch ----------------
__device__ __align__(16) __half g_Whh[(size_t)8192 * 2048];   // fp16 Wh  (33.5 MB)
__device__ __align__(16) __half g_Wmh[(size_t)2048 * 2048];   // fp16 Wm  ( 8.4 MB)
__device__ __align__(16) __half g_inh[(size_t)8192 * 2048];   // fp16 inputs
__device__ __align__(16) __half g_wxh[(size_t)10240 * 2048];  // fp16 Wx
__device__ float  g_xg[(size_t)T_STEPS * NCOL];               // input projections
__device__ __align__(16) float  g_h[2][MEM];                  // fp32 h
__device__ __align__(16) __half g_hh[2][MEM];                 // fp16 h (exchange)
__device__ __align__(16) __half g_mh[MEM];                    // fp16 m (exchange)
__device__ unsigned int g_bar1;
__device__ unsigned int g_bar2;

// ---------------- init (graph-replay safe) ----------------
__global__ void k_init() {
    int i = blockIdx.x * blockDim.x + threadIdx.x;
    if (i == 0) { g_bar1 = 0u; g_bar2 = 0u; }
    if (i < MEM) {
        g_h[0][i] = 0.f; g_h[1][i] = 0.f;
        g_hh[0][i] = __float2half_rn(0.f);
        g_hh[1][i] = __float2half_rn(0.f);
        g_mh[i]    = __float2half_rn(0.f);
    }
}

// ---------------- fp32 -> fp16 conversions ----------------
__global__ void k_convert(const float* __restrict__ Wh, const float* __restrict__ Wm) {
    const int n1 = 8192 * 2048, n2 = 2048 * 2048;
    int stride = gridDim.x * blockDim.x;
    for (int i = blockIdx.x * blockDim.x + threadIdx.x; i < n1; i += stride)
        g_Whh[i] = __float2half_rn(Wh[i]);
    for (int i = blockIdx.x * blockDim.x + threadIdx.x; i < n2; i += stride)
        g_Wmh[i] = __float2half_rn(Wm[i]);
}
__global__ void k_convert2(const float* __restrict__ inp, const float* __restrict__ Wx) {
    const int n1 = 8192 * 2048, n2 = 10240 * 2048;
    int stride = gridDim.x * blockDim.x;
    for (int i = blockIdx.x * blockDim.x + threadIdx.x; i < n1; i += stride)
        g_inh[i] = __float2half_rn(inp[i]);
    for (int i = blockIdx.x * blockDim.x + threadIdx.x; i < n2; i += stride)
        g_wxh[i] = __float2half_rn(Wx[i]);
}

// ---------------- cp.async helpers ----------------
__device__ __forceinline__ void cp_async16(unsigned smem, const void* gptr) {
    asm volatile("cp.async.cg.shared.global [%0], [%1], 16;" :: "r"(smem), "l"(gptr));
}
__device__ __forceinline__ void cp_commit() { asm volatile("cp.async.commit_group;"); }
__device__ __forceinline__ void cp_wait1()  { asm volatile("cp.async.wait_group 1;"); }
__device__ __forceinline__ void cp_wait0()  { asm volatile("cp.async.wait_group 0;"); }

// ---------------- tensor-core GEMM (2-stage cp.async, K-tile = 64: half the barriers) ----------------
// C[8192,10240] = A[8192,2048]fp16 * B[10240,2048]^T fp16, fp32 accum.
// 128x128x64 CTA tile, 8 warps (2x4), 64x32 warp tile, mma.m16n8k16.
// Same fragment math and identical global k-accumulation order as the
// validated 32-wide version -> bit-identical output.
#define LDT 72   // 64 halves + 8 pad: bank = grp*4+tig (mod 32), conflict-free
#define GEMM_SMEM (2 * 2 * 128 * LDT * 2)   // 2 stages x (A+B) x 128 rows -> 73,728 B

__global__ __launch_bounds__(256) void k_gemm16(const __half* __restrict__ A,
                                                const __half* __restrict__ B,
                                                const float* __restrict__ bias) {
    extern __shared__ __align__(16) __half gsm[];
    __half* As = gsm;                       // 2 stages x 128*LDT
    __half* Bs = gsm + 2 * 128 * LDT;       // 2 stages x 128*LDT
    const int tid = threadIdx.x;
    const int warp = tid >> 5, lane = tid & 31;
    const int bm = blockIdx.y * 128, bn = blockIdx.x * 128;
    const int wm = (warp >> 2) * 64, wn = (warp & 3) * 32;
    const int grp = lane >> 2, tig = lane & 3;

    const unsigned sA = (unsigned)__cvta_generic_to_shared(As);
    const unsigned sB = (unsigned)__cvta_generic_to_shared(Bs);
    const unsigned stageBytes = 128 * LDT * 2;

    float acc[4][4][4];
#pragma unroll
    for (int mt = 0; mt < 4; mt++)
#pragma unroll
        for (int nt = 0; nt < 4; nt++)
#pragma unroll
            for (int k = 0; k < 4; k++) acc[mt][nt][k] = 0.f;

    // loader mapping: 128 rows x 64 halves = 1024 x 16B chunks per matrix,
    // 256 threads x 4 chunks each; row = idx>>3, c8 = idx&7
    auto issue = [&](int k0, int s) {
#pragma unroll
        for (int j = 0; j < 4; j++) {
            int idx = tid + j * 256;
            int row = idx >> 3, c8 = idx & 7;
            cp_async16(sA + s * stageBytes + (row * LDT + c8 * 8) * 2,
                       A + (size_t)(bm + row) * IN_DIM + k0 + c8 * 8);
            cp_async16(sB + s * stageBytes + (row * LDT + c8 * 8) * 2,
                       B + (size_t)(bn + row) * IN_DIM + k0 + c8 * 8);
        }
        cp_commit();
    };

    const int NTILE = IN_DIM / 64;   // 32
    issue(0, 0);

    for (int it = 0; it < NTILE; ++it) {
        int s = it & 1;
        if (it + 1 < NTILE) { issue((it + 1) * 64, s ^ 1); cp_wait1(); }
        else                { cp_wait0(); }
        __syncthreads();

        const __half* Ab = &As[s * 128 * LDT];
        const __half* Bb = &Bs[s * 128 * LDT];
#pragma unroll
        for (int ks = 0; ks < 64; ks += 16) {
            unsigned bf[4][2];
#pragma unroll
            for (int nt = 0; nt < 4; nt++) {
                const __half* bp = &Bb[(wn + nt * 8 + grp) * LDT + tig * 2 + ks];
                bf[nt][0] = *(const unsigned*)bp;
                bf[nt][1] = *(const unsigned*)(bp + 8);
            }
#pragma unroll
            for (int mt = 0; mt < 4; mt++) {
                const __half* ap = &Ab[(wm + mt * 16 + grp) * LDT + tig * 2 + ks];
                unsigned a0 = *(const unsigned*)ap;
                unsigned a1 = *(const unsigned*)(ap + 8 * LDT);
                unsigned a2 = *(const unsigned*)(ap + 8);
                unsigned a3 = *(const unsigned*)(ap + 8 * LDT + 8);
#pragma unroll
                for (int nt = 0; nt < 4; nt++) {
                    asm volatile(
                        "mma.sync.aligned.m16n8k16.row.col.f32.f16.f16.f32 "
                        "{%0,%1,%2,%3}, {%4,%5,%6,%7}, {%8,%9}, {%0,%1,%2,%3};"
                        : "+f"(acc[mt][nt][0]), "+f"(acc[mt][nt][1]),
                          "+f"(acc[mt][nt][2]), "+f"(acc[mt][nt][3])
                        : "r"(a0), "r"(a1), "r"(a2), "r"(a3),
                          "r"(bf[nt][0]), "r"(bf[nt][1]));
                }
            }
        }
        __syncthreads();
    }

    // ---- epilogue: + bias, fp32 store ----
#pragma unroll
    for (int mt = 0; mt < 4; mt++) {
        int m = bm + wm + mt * 16 + grp;
#pragma unroll
        for (int nt = 0; nt < 4; nt++) {
            int n = bn + wn + nt * 8 + tig * 2;
            float2 bv = *(const float2*)(bias + n);
            float2 o0 = { acc[mt][nt][0] + bv.x, acc[mt][nt][1] + bv.y };
            float2 o1 = { acc[mt][nt][2] + bv.x, acc[mt][nt][3] + bv.y };
            *(float2*)(g_xg + (size_t)m * NCOL + n) = o0;
            *(float2*)(g_xg + (size_t)(m + 8) * NCOL + n) = o1;
        }
    }
}

// ---------------- sync / load / math helpers ----------------
__device__ __forceinline__ unsigned ld_relaxed(const unsigned* p) {
    unsigned v;
    asm volatile("ld.relaxed.gpu.global.u32 %0, [%1];" : "=r"(v) : "l"(p) : "memory");
    return v;
}
__device__ __forceinline__ unsigned ld_acq(const unsigned* p) {
    unsigned v;
    asm volatile("ld.acquire.gpu.global.u32 %0, [%1];" : "=r"(v) : "l"(p) : "memory");
    return v;
}
__device__ __forceinline__ void red_rel(unsigned* p) {
    asm volatile("red.release.gpu.global.add.u32 [%0], 1;" :: "l"(p) : "memory");
}
__device__ __forceinline__ unsigned ldcg1(const unsigned* p) {
    unsigned v;
    asm volatile("ld.global.cg.u32 %0, [%1];" : "=r"(v) : "l"(p) : "memory");
    return v;
}
__device__ __forceinline__ float sigf(float x) { return 1.0f / (1.0f + __expf(-x)); }
// fast tanh via MUFU EX2+RCP (validated R8/R9/R12)
__device__ __forceinline__ float tanhf_fast(float x) {
    return 1.0f - __fdividef(2.0f, 1.0f + __expf(2.0f * x));
}
__device__ __forceinline__ float wsum(float v) {
#pragma unroll
    for (int o = 16; o > 0; o >>= 1) v += __shfl_xor_sync(0xffffffffu, v, o);
    return v;
}
__device__ __forceinline__ __half2 h2u(unsigned u) { return *reinterpret_cast<__half2*>(&u); }

__device__ __forceinline__ void mac8(uint4 wv, uint4 hv, float& ax, float& ay) {
    __half2 p = __hmul2(h2u(wv.x), h2u(hv.x));
    p = __hfma2(h2u(wv.y), h2u(hv.y), p);
    p = __hfma2(h2u(wv.z), h2u(hv.z), p);
    p = __hfma2(h2u(wv.w), h2u(hv.w), p);
    float2 f = __half22float2(p);
    ax += f.x; ay += f.y;
}

// ---------------- persistent recurrent kernel (R12: validated optimum, byte-identical) ----------------
#define DYN_SMEM (42 * 4096 + 4096 + 4096)

__global__ __launch_bounds__(NT, 1) void k_recur(const float* __restrict__ bh,
                                                 const float* __restrict__ bmv,
                                                 float* __restrict__ out) {
    extern __shared__ __align__(16) unsigned char dyn[];
    __half* s_w  = (__half*)dyn;                       // 42 iof rows x 2048 fp16
    __half* s_hv = (__half*)(dyn + 42 * 4096);         // staged h
    __half* s_mv = (__half*)(dyn + 42 * 4096 + 4096);  // staged m
    __shared__ float s_pre[42];

    const int b = blockIdx.x;
    const int tid = threadIdx.x;
    const int w = tid >> 5, lane = tid & 31;
    const int nu = (b < 124) ? 14 : 13;                // unit j = b + r*148, r < nu
    const bool act = (w < nu);
    const int nbrows = 3 * nu;

    // ---- preload ALL iof weight rows into SMEM ----
    for (int idx = tid; idx < nbrows * 256; idx += NT) {
        int d = idx >> 8, col = idx & 255;
        int g = d / nu, r = d - g * nu;
        int base = (g == 0) ? 0 : (g == 1) ? 2048 : 6144;
        ((uint4*)s_w)[idx] =
            *((const uint4*)(g_Whh + (size_t)(base + b + r * 148) * 2048) + col);
    }

    // ---- per-warp: z-row + Wm-row into registers ----
    uint4 zr[8], mr[8];
    const int j0 = act ? (b + w * 148) : 0;
    float bhz = 0.f, bmu = 0.f, c0 = 0.f;
    if (act) {
        const uint4* pz = (const uint4*)(g_Whh + (size_t)(4096 + j0) * 2048);
        const uint4* pm = (const uint4*)(g_Wmh + (size_t)j0 * 2048);
#pragma unroll
        for (int i = 0; i < 8; i++) {
            zr[i] = __ldg(pz + i * 32 + lane);
            mr[i] = __ldg(pm + i * 32 + lane);
        }
        bhz = bh[4096 + j0];
        bmu = bmv[j0];
    } else {
#pragma unroll
        for (int i = 0; i < 8; i++) { zr[i] = make_uint4(0,0,0,0); mr[i] = make_uint4(0,0,0,0); }
    }

    // ---- per-warp: 3 iof rows + biases ----
    const int d0 = w * 3;
    float bb0 = 0.f, bb1 = 0.f, bb2 = 0.f;
    const bool iof_act = (d0 < nbrows);
    if (iof_act) {
#pragma unroll
        for (int k = 0; k < 3; k++) {
            int d = d0 + k, g = d / nu, r = d - g * nu;
            int base = (g == 0) ? 0 : (g == 1) ? 2048 : 6144;
            float bv = bh[base + b + r * 148];
            if (k == 0) bb0 = bv; else if (k == 1) bb1 = bv; else bb2 = bv;
        }
    }

    // ---- xg prefetch for t=0 ----
    float zx = 0.f, ixv = 0.f, oxv = 0.f, fxv = 0.f, uxv = 0.f;
    if (act) {
        const float* xg = g_xg;
        zx  = __ldg(xg + 4096 + j0);
        ixv = __ldg(xg + j0);
        oxv = __ldg(xg + 2048 + j0);
        fxv = __ldg(xg + 6144 + j0);
        uxv = __ldg(xg + 8192 + j0);
    }
    __syncthreads();

    int cur = 0;
    for (int t = 0; t < T_STEPS; ++t) {
        // ---- wait for all h(t-1) publications (single poller), stage h ----
        if (tid == 0 && t) {
            const unsigned tgt = (unsigned)t * (unsigned)NCTA;
            while (ld_relaxed(&g_bar2) < tgt) {}
            (void)ld_acq(&g_bar2);
        }
        __syncthreads();
        {
            const unsigned* src = (const unsigned*)g_hh[cur];
            unsigned* dst = (unsigned*)s_hv;
#pragma unroll
            for (int i = tid; i < 1024; i += NT) dst[i] = ldcg1(src + i);
        }
        __syncthreads();

        const uint4* hh = (const uint4*)s_hv;

        // ---- Phase A: z dot (register weights, SMEM h) ----
        {
            float ax = 0.f, ay = 0.f;
#pragma unroll
            for (int i = 0; i < 8; i++) mac8(zr[i], hh[i * 32 + lane], ax, ay);
            float z = wsum(ax + ay);
            if (act && lane == 0) {
                float m = sigf(z + bhz + zx) * tanhf_fast(c0);
                g_mh[j0] = __float2half_rn(m);
            }
        }
        __syncthreads();                        // all m stores done
        if (tid == 0) red_rel(&g_bar1);         // publish m (1 release/CTA)

        // ---- Phase B: 3 iof rows (SMEM weights) -- hides bar1 propagation ----
        if (iof_act) {
            const uint4* q0 = (const uint4*)(s_w + (size_t)(d0 + 0) * 2048);
            const uint4* q1 = (const uint4*)(s_w + (size_t)(d0 + 1) * 2048);
            const uint4* q2 = (const uint4*)(s_w + (size_t)(d0 + 2) * 2048);
            float s0x = 0.f, s0y = 0.f, s1x = 0.f, s1y = 0.f, s2x = 0.f, s2y = 0.f;
#pragma unroll
            for (int i = 0; i < 8; i++) {
                uint4 hv = hh[i * 32 + lane];
                mac8(q0[i * 32 + lane], hv, s0x, s0y);
                mac8(q1[i * 32 + lane], hv, s1x, s1y);
                mac8(q2[i * 32 + lane], hv, s2x, s2y);
            }
            float p0 = wsum(s0x + s0y);
            float p1 = wsum(s1x + s1y);
            float p2 = wsum(s2x + s2y);
            if (lane == 0) {
                s_pre[d0 + 0] = p0 + bb0;
                s_pre[d0 + 1] = p1 + bb1;
                s_pre[d0 + 2] = p2 + bb2;
            }
        }

        // ---- bar1 wait (single poller) + stage m into SMEM ----
        if (tid == 0) {
            const unsigned tgt1 = (unsigned)(t + 1) * (unsigned)NCTA;
            while (ld_relaxed(&g_bar1) < tgt1) {}
            (void)ld_acq(&g_bar1);
        }
        __syncthreads();
        {
            const unsigned* src = (const unsigned*)g_mh;
            unsigned* dst = (unsigned*)s_mv;
#pragma unroll
            for (int i = tid; i < 1024; i += NT) dst[i] = ldcg1(src + i);
        }
        __syncthreads();

        // ---- Phase C: Wm dot (register weights, SMEM m) ----
        float u = 0.f;
        {
            const uint4* mm = (const uint4*)s_mv;
            float ux = 0.f, uy = 0.f;
#pragma unroll
            for (int i = 0; i < 8; i++) mac8(mr[i], mm[i * 32 + lane], ux, uy);
            u = wsum(ux + uy);
        }

        // ---- gates + cell update + publish h ----
        if (act) {
            float i_ = sigf(ixv + s_pre[w]);
            float o_ = sigf(oxv + s_pre[nu + w]);
            float f_ = sigf(fxv + s_pre[2 * nu + w]);
            float uu = tanhf_fast(uxv + u + bmu);
            c0 = i_ * uu + f_ * c0;
            float hn = o_ * tanhf_fast(c0);
            if (lane == 0) {
                int nxt = cur ^ 1;
                g_h[nxt][j0]  = hn;
                g_hh[nxt][j0] = __float2half_rn(hn);
            }
        }
        __syncthreads();                        // all h stores done
        if (tid == 0) red_rel(&g_bar2);         // publish h (1 release/CTA)

        // ---- xg prefetch for t+1 (hidden under next bar2 wait) ----
        if (act && t + 1 < T_STEPS) {
            const float* xg = g_xg + (size_t)(t + 1) * NCOL;
            zx  = __ldg(xg + 4096 + j0);
            ixv = __ldg(xg + j0);
            oxv = __ldg(xg + 2048 + j0);
            fxv = __ldg(xg + 6144 + j0);
            uxv = __ldg(xg + 8192 + j0);
        }
        cur ^= 1;
    }

    // ---- output: h_T (CTA 0 copies after all final writes land) ----
    if (b == 0) {
        if (tid == 0) {
            const unsigned tgt = (unsigned)NCTA * (unsigned)T_STEPS;
            while (ld_relaxed(&g_bar2) < tgt) {}
            (void)ld_acq(&g_bar2);
        }
        __syncthreads();
        for (int i = tid; i < MEM; i += NT) out[i] = g_h[T_STEPS & 1][i];
    }
}

// ---------------- launch ----------------
extern "C" void kernel_launch(void* const* d_in, const int* in_sizes, int n_in,
                              void* d_out, int out_size) {
    const float* inputs = (const float*)d_in[0];
    const float* Wx     = (const float*)d_in[1];
    const float* bx     = (const float*)d_in[2];
    const float* Wh     = (const float*)d_in[3];
    const float* bh     = (const float*)d_in[4];
    const float* Wm     = (const float*)d_in[5];
    const float* bm     = (const float*)d_in[6];
    float* out = (float*)d_out;

    cudaFuncSetAttribute(k_recur, cudaFuncAttributeMaxDynamicSharedMemorySize, DYN_SMEM);
    cudaFuncSetAttribute(k_gemm16, cudaFuncAttributeMaxDynamicSharedMemorySize, GEMM_SMEM);

    __half* inh; cudaGetSymbolAddress((void**)&inh, g_inh);
    __half* wxh; cudaGetSymbolAddress((void**)&wxh, g_wxh);

    k_init<<<8, 256>>>();
    k_convert<<<2048, 256>>>(Wh, Wm);
    k_convert2<<<2048, 256>>>(inputs, Wx);
    k_gemm16<<<dim3(NCOL / 128, T_STEPS / 128), 256, GEMM_SMEM>>>(inh, wxh, bx);
    k_recur<<<NCTA, NT, DYN_SMEM>>>(bh, bm, out);
}